// round 2
// baseline (speedup 1.0000x reference)
#include <cuda_runtime.h>
#include <math.h>

#define B_  128
#define T_  64
#define F_  2048
#define H_  1024
#define M_  512
#define G4  4096   // 4*H
#define NA  4608   // 4H + M
#define K2  2048   // 2H

// ---------------- scratch (device globals; no allocations allowed) ----------
__device__ float d_V  [B_*T_*H_];          // relu(embed)
__device__ float d_VT [B_*T_*H_];          // time-major [T,B,H]
__device__ float d_GXZ[(size_t)B_*T_*NA];  // x @ [W_ih1;Wsi]^T + [b1;b_bd], [T,B,NA]
__device__ float d_Wh [NA*H_];             // [W_hh1; Wsh]
__device__ float d_Wx [NA*H_];             // [W_ih1; Wsi]
__device__ float d_bx [NA];                // [b1; b_bd]
__device__ float d_Wb [(size_t)G4*K2];     // [W_ih2 | W_hh2] along K
__device__ float d_Y1 [B_*NA];
__device__ float d_Y2 [B_*G4];
__device__ float d_h1 [B_*H_];
__device__ float d_c1 [B_*H_];
__device__ float d_c2 [B_*H_];
__device__ float d_h1r[B_*H_];
__device__ float d_c1r[B_*H_];
__device__ float d_ST [B_*K2];             // [h1raw*s | h2]
__device__ float d_s  [B_];
__device__ float d_dummy[B_*H_];

// ---------------- generic fp32 GEMM: C[M,N] = A[M,K] @ B[N,K]^T (+bias)(+Cin)(relu)
// BM=128 fixed, BK=16 fixed, 128 threads, thread grid 16x8, TM=8.
template<int BN, int TN>
__global__ __launch_bounds__(128)
void gemm_nt(const float* __restrict__ A, const float* __restrict__ Bw,
             float* __restrict__ C, const float* __restrict__ Cin,
             const float* __restrict__ bias, int K, int N, int relu)
{
    constexpr int BM = 128, BK = 16, TM = 8;
    constexpr int NF4 = (BN * BK / 4) / 128;   // float4s of B per thread (2 for BN=64, 1 for BN=32)
    __shared__ float As[BK][BM];
    __shared__ float Bs[BK][BN];

    const int tid = threadIdx.x;
    const int tc  = tid & 7;     // 0..7   (col group)
    const int tr  = tid >> 3;    // 0..15  (row group)

    const float* Ab = A  + (size_t)blockIdx.y * BM * K;
    const float* Bb = Bw + (size_t)blockIdx.x * BN * K;

    float acc[TM][TN];
#pragma unroll
    for (int i = 0; i < TM; i++)
#pragma unroll
        for (int j = 0; j < TN; j++) acc[i][j] = 0.f;

    for (int k0 = 0; k0 < K; k0 += BK) {
        // global loads into registers
        float4 aR[4];
        const float4* ap = reinterpret_cast<const float4*>(Ab + (size_t)tid * K + k0);
#pragma unroll
        for (int v = 0; v < 4; v++) aR[v] = ap[v];

        float4 bR[NF4];
#pragma unroll
        for (int v = 0; v < NF4; v++) {
            int f = tid * NF4 + v;
            int row = f >> 2, p = f & 3;
            bR[v] = *reinterpret_cast<const float4*>(Bb + (size_t)row * K + k0 + p * 4);
        }

        __syncthreads();   // previous tile fully consumed
#pragma unroll
        for (int v = 0; v < 4; v++) {
            As[v*4+0][tid] = aR[v].x; As[v*4+1][tid] = aR[v].y;
            As[v*4+2][tid] = aR[v].z; As[v*4+3][tid] = aR[v].w;
        }
#pragma unroll
        for (int v = 0; v < NF4; v++) {
            int f = tid * NF4 + v;
            int row = f >> 2, p = f & 3;
            Bs[p*4+0][row] = bR[v].x; Bs[p*4+1][row] = bR[v].y;
            Bs[p*4+2][row] = bR[v].z; Bs[p*4+3][row] = bR[v].w;
        }
        __syncthreads();

#pragma unroll
        for (int kk = 0; kk < BK; kk++) {
            float ar[TM], br[TN];
#pragma unroll
            for (int i = 0; i < TM; i++) ar[i] = As[kk][tr*TM + i];
#pragma unroll
            for (int j = 0; j < TN; j++) br[j] = Bs[kk][tc*TN + j];
#pragma unroll
            for (int i = 0; i < TM; i++)
#pragma unroll
                for (int j = 0; j < TN; j++)
                    acc[i][j] = fmaf(ar[i], br[j], acc[i][j]);
        }
    }

    const int rowBase = blockIdx.y * BM + tr * TM;
    const int colBase = blockIdx.x * BN + tc * TN;
#pragma unroll
    for (int i = 0; i < TM; i++) {
        size_t off = (size_t)(rowBase + i) * N + colBase;
#pragma unroll
        for (int j = 0; j < TN; j++) {
            float v = acc[i][j];
            if (bias) v += bias[colBase + j];
            if (Cin)  v += Cin[off + j];
            if (relu) v = fmaxf(v, 0.f);
            C[off + j] = v;
        }
    }
}

// ---------------- helpers -----------------------------------------------
__device__ __forceinline__ float sigm(float x) { return 1.f / (1.f + expf(-x)); }

__global__ void zero_state()
{
    int idx = blockIdx.x * blockDim.x + threadIdx.x;
    if (idx < B_*H_) { d_h1[idx] = 0.f; d_c1[idx] = 0.f; d_c2[idx] = 0.f; }
    if (idx < B_*K2) d_ST[idx] = 0.f;
}

__global__ void pack_h(const float* __restrict__ Whh1, const float* __restrict__ Wsh)
{
    int idx = blockIdx.x * blockDim.x + threadIdx.x;
    if (idx >= NA*H_) return;
    d_Wh[idx] = (idx < G4*H_) ? Whh1[idx] : Wsh[idx - G4*H_];
}

__global__ void pack_x(const float* __restrict__ Wih1, const float* __restrict__ Wsi,
                       const float* __restrict__ b1,   const float* __restrict__ bbd)
{
    int idx = blockIdx.x * blockDim.x + threadIdx.x;
    if (idx < NA*H_)
        d_Wx[idx] = (idx < G4*H_) ? Wih1[idx] : Wsi[idx - G4*H_];
    if (idx < NA)
        d_bx[idx] = (idx < G4) ? b1[idx] : bbd[idx - G4];
}

__global__ void pack_b(const float* __restrict__ Wih2, const float* __restrict__ Whh2)
{
    size_t idx = (size_t)blockIdx.x * blockDim.x + threadIdx.x;
    if (idx >= (size_t)G4*K2) return;
    int n = (int)(idx >> 11), k = (int)(idx & (K2 - 1));
    d_Wb[idx] = (k < H_) ? Wih2[(size_t)n*H_ + k] : Whh2[(size_t)n*H_ + (k - H_)];
}

__global__ void transpose_tb()   // d_VT[t*B+b][h] = d_V[b*T+t][h]
{
    int idx = blockIdx.x * blockDim.x + threadIdx.x;
    if (idx >= B_*T_*H_) return;
    int h = idx & (H_ - 1);
    int r = idx >> 10;        // dest row = t*B + b
    int t = r >> 7;
    int b = r & 127;
    d_VT[idx] = d_V[((size_t)(b * T_ + t)) * H_ + h];
}

// per-step: boundary gate + LSTM1 activations (one CTA per batch row)
__global__ void act_a(const float* __restrict__ vs)
{
    int b = blockIdx.x;
    int tid = threadIdx.x;
    const float* Yb = d_Y1 + (size_t)b * NA;
    __shared__ float red[256];

    float p = Yb[G4 + tid] * vs[tid] + Yb[G4 + 256 + tid] * vs[256 + tid];
    red[tid] = p;
    __syncthreads();
    for (int off = 128; off > 0; off >>= 1) {
        if (tid < off) red[tid] += red[tid + off];
        __syncthreads();
    }
    float s = rintf(1.f / (1.f + expf(-red[0])));   // round-half-even, matches jnp.round
    if (tid == 0) d_s[b] = s;

    for (int j = tid; j < H_; j += 256) {
        float gi = Yb[j], gf = Yb[H_ + j], gg = Yb[2*H_ + j], go = Yb[3*H_ + j];
        float c = sigm(gf) * d_c1[b*H_ + j] + sigm(gi) * tanhf(gg);
        float h = sigm(go) * tanhf(c);
        d_c1r[b*H_ + j] = c;
        d_h1r[b*H_ + j] = h;
        d_ST[b*K2 + j] = h * s;       // lstm2 input
    }
}

// per-step: LSTM2 activations + state commits
__global__ void act_b(float* __restrict__ out2)
{
    int idx = blockIdx.x * blockDim.x + threadIdx.x;
    if (idx >= B_*H_) return;
    int b = idx >> 10, j = idx & (H_ - 1);
    const float* Yb = d_Y2 + (size_t)b * G4;
    float gi = Yb[j], gf = Yb[H_ + j], gg = Yb[2*H_ + j], go = Yb[3*H_ + j];
    float c = sigm(gf) * d_c2[idx] + sigm(gi) * tanhf(gg);
    float h = sigm(go) * tanhf(c);
    d_c2[idx] = c;
    d_ST[b*K2 + H_ + j] = h;          // h2 for next step's GEMM_B
    out2[idx] = h;
    float s = d_s[b];
    d_h1[idx] = d_h1r[idx] * (1.f - s);
    d_c1[idx] = d_c1r[idx] * (1.f - s);
}

// ---------------- launch -----------------------------------------------
extern "C" void kernel_launch(void* const* d_in, const int* in_sizes, int n_in,
                              void* d_out, int out_size)
{
    const float* video = (const float*)d_in[0];
    const float* Wemb  = (const float*)d_in[1];
    const float* bemb  = (const float*)d_in[2];
    const float* Wih1  = (const float*)d_in[3];
    const float* Whh1  = (const float*)d_in[4];
    const float* b1    = (const float*)d_in[5];
    const float* Wsi   = (const float*)d_in[6];
    const float* Wsh   = (const float*)d_in[7];
    const float* bbd   = (const float*)d_in[8];
    const float* vs    = (const float*)d_in[9];
    const float* Wih2  = (const float*)d_in[10];
    const float* Whh2  = (const float*)d_in[11];

    float *pV, *pVT, *pGXZ, *pWh, *pWx, *pbx, *pWb, *pY1, *pY2, *ph1, *pST, *pdum;
    cudaGetSymbolAddress((void**)&pV,   d_V);
    cudaGetSymbolAddress((void**)&pVT,  d_VT);
    cudaGetSymbolAddress((void**)&pGXZ, d_GXZ);
    cudaGetSymbolAddress((void**)&pWh,  d_Wh);
    cudaGetSymbolAddress((void**)&pWx,  d_Wx);
    cudaGetSymbolAddress((void**)&pbx,  d_bx);
    cudaGetSymbolAddress((void**)&pWb,  d_Wb);
    cudaGetSymbolAddress((void**)&pY1,  d_Y1);
    cudaGetSymbolAddress((void**)&pY2,  d_Y2);
    cudaGetSymbolAddress((void**)&ph1,  d_h1);
    cudaGetSymbolAddress((void**)&pST,  d_ST);
    cudaGetSymbolAddress((void**)&pdum, d_dummy);

    // prep: states, packed weights
    zero_state<<<(B_*K2 + 255) / 256, 256>>>();
    pack_h<<<(NA*H_ + 255) / 256, 256>>>(Whh1, Wsh);
    pack_x<<<(NA*H_ + 255) / 256, 256>>>(Wih1, Wsi, b1, bbd);
    pack_b<<<(int)(((size_t)G4*K2 + 255) / 256), 256>>>(Wih2, Whh2);

    // V = relu(video @ W_embed^T + b_embed)      [8192,1024]
    gemm_nt<64, 8><<<dim3(H_/64, (B_*T_)/128), 128>>>(video, Wemb, pV, nullptr, bemb, F_, H_, 1);
    // time-major
    transpose_tb<<<(B_*T_*H_ + 255) / 256, 256>>>();
    // GXZ = VT @ [W_ih1;Wsi]^T + [b1;b_bd]       [8192,4608]
    gemm_nt<64, 8><<<dim3(NA/64, (B_*T_)/128), 128>>>(pVT, pWx, pGXZ, nullptr, pbx, H_, NA, 0);

    // sequential scan over T
    for (int t = 0; t < T_; t++) {
        // Y1 = h1 @ [W_hh1;Wsh]^T + GXZ[t]
        gemm_nt<32, 4><<<dim3(NA/32, 1), 128>>>(ph1, pWh, pY1,
                                                pGXZ + (size_t)t * B_ * NA, nullptr, H_, NA, 0);
        act_a<<<B_, 256>>>(vs);
        // Y2 = [h1raw*s | h2] @ [W_ih2 | W_hh2]^T   (K = 2048)
        gemm_nt<32, 4><<<dim3(G4/32, 1), 128>>>(pST, pWb, pY2, nullptr, nullptr, K2, G4, 0);
        act_b<<<(B_*H_ + 255) / 256, 256>>>(t == T_-1 ? (float*)d_out : pdum);
    }
}

// round 3
// speedup vs baseline: 1.4474x; 1.4474x over previous
#include <cuda_runtime.h>
#include <math.h>

#define B_  128
#define T_  64
#define F_  2048
#define H_  1024
#define M_  512
#define G4  4096   // 4*H
#define NA  4608   // 4H + M
#define K2  2048   // 2H

// ---------------- scratch (device globals; no allocations allowed) ----------
__device__ float d_V  [B_*T_*H_];          // relu(embed), [B,T,H]
__device__ float d_GXZ[(size_t)B_*T_*NA];  // x @ [W_ih1;Wsi]^T + [b1;b_bd], [T,B,NA]
__device__ float d_Wh [NA*H_];             // [W_hh1; Wsh]
__device__ float d_Wx [NA*H_];             // [W_ih1; Wsi]
__device__ float d_bx [NA];                // [b1; b_bd]
__device__ float d_Wb [(size_t)G4*K2];     // [W_ih2 | W_hh2] along K
__device__ float d_Y1 [B_*NA];
__device__ float d_Y2 [B_*G4];
__device__ float d_h1 [B_*H_];
__device__ float d_c1 [B_*H_];
__device__ float d_c2 [B_*H_];
__device__ float d_h1r[B_*H_];
__device__ float d_c1r[B_*H_];
__device__ float d_ST [B_*K2];             // [h1raw*s | h2]
__device__ float d_s  [B_];
__device__ float d_dummy[B_*H_];

// =====================================================================
// gemm_big: C[M,N] = relu?(A @ Bw^T + bias)
// BM=128, BN=128, BK=8, 256 threads, TM=8, TN=8, double-buffered.
// A row mapping: row (tile y, r) at A + y*tileStride + r*lda.
// C rows contiguous: row = y*128 + r.
// =====================================================================
template<int RELU>
__global__ __launch_bounds__(256, 2)
void gemm_big(const float* __restrict__ A, size_t tileStride, int lda,
              const float* __restrict__ Bw, float* __restrict__ C,
              const float* __restrict__ bias, int K, int N)
{
    constexpr int BM = 128, BN = 128, BK = 8, PAD = 132;
    __shared__ float As[2][BK][PAD];
    __shared__ float Bs[2][BK][PAD];

    const int tid = threadIdx.x;
    const int tr  = tid >> 4;        // 0..15
    const int tc  = tid & 15;        // 0..15
    const int lr  = tid >> 1;        // 0..127
    const int lk  = (tid & 1) * 4;   // 0 or 4

    const float* Ab = A + (size_t)blockIdx.y * tileStride + (size_t)lr * lda + lk;
    const float* Bb = Bw + (size_t)(blockIdx.x * BN + lr) * K + lk;

    float acc[8][8];
#pragma unroll
    for (int i = 0; i < 8; i++)
#pragma unroll
        for (int j = 0; j < 8; j++) acc[i][j] = 0.f;

    float4 aR = *reinterpret_cast<const float4*>(Ab);
    float4 bR = *reinterpret_cast<const float4*>(Bb);
#pragma unroll
    for (int j = 0; j < 4; j++) {
        As[0][lk + j][lr] = (&aR.x)[j];
        Bs[0][lk + j][lr] = (&bR.x)[j];
    }
    __syncthreads();

    const int KT = K / BK;
    for (int kt = 0; kt < KT; kt++) {
        const int p = kt & 1;
        if (kt + 1 < KT) {
            aR = *reinterpret_cast<const float4*>(Ab + (kt + 1) * BK);
            bR = *reinterpret_cast<const float4*>(Bb + (kt + 1) * BK);
        }
#pragma unroll
        for (int kk = 0; kk < BK; kk++) {
            float a[8], b[8];
            *reinterpret_cast<float4*>(a)     = *reinterpret_cast<const float4*>(&As[p][kk][tr * 8]);
            *reinterpret_cast<float4*>(a + 4) = *reinterpret_cast<const float4*>(&As[p][kk][tr * 8 + 4]);
            *reinterpret_cast<float4*>(b)     = *reinterpret_cast<const float4*>(&Bs[p][kk][tc * 8]);
            *reinterpret_cast<float4*>(b + 4) = *reinterpret_cast<const float4*>(&Bs[p][kk][tc * 8 + 4]);
#pragma unroll
            for (int i = 0; i < 8; i++)
#pragma unroll
                for (int j = 0; j < 8; j++)
                    acc[i][j] = fmaf(a[i], b[j], acc[i][j]);
        }
        if (kt + 1 < KT) {
#pragma unroll
            for (int j = 0; j < 4; j++) {
                As[p ^ 1][lk + j][lr] = (&aR.x)[j];
                Bs[p ^ 1][lk + j][lr] = (&bR.x)[j];
            }
        }
        __syncthreads();
    }

    const int colBase = blockIdx.x * BN + tc * 8;
#pragma unroll
    for (int i = 0; i < 8; i++) {
        const int row = blockIdx.y * BM + tr * 8 + i;
        size_t off = (size_t)row * N + colBase;
        float o[8];
#pragma unroll
        for (int j = 0; j < 8; j++) {
            float v = acc[i][j] + bias[colBase + j];
            o[j] = RELU ? fmaxf(v, 0.f) : v;
        }
        *reinterpret_cast<float4*>(&C[off])     = *reinterpret_cast<float4*>(o);
        *reinterpret_cast<float4*>(&C[off + 4]) = *reinterpret_cast<float4*>(o + 4);
    }
}

// =====================================================================
// gemm_seq: C[128,N] = A[128,K] @ Bw[N,K]^T (+ Cin)
// BM=128 (whole batch), BN=32, BK=32, 256 threads, TM=4, TN=4.
// =====================================================================
__global__ __launch_bounds__(256)
void gemm_seq(const float* __restrict__ A, const float* __restrict__ Bw,
              float* __restrict__ C, const float* __restrict__ Cin,
              int K, int N)
{
    constexpr int BN = 32, BK = 32, PAD = 132, PADB = 36;
    __shared__ float As[2][BK][PAD];
    __shared__ float Bs[2][BK][PADB];

    const int tid = threadIdx.x;
    const int tr  = tid >> 3;        // 0..31
    const int tc  = tid & 7;         // 0..7
    const int lrA = tid >> 1;        // 0..127
    const int lkA = (tid & 1) * 16;
    const int lrB = tid >> 3;        // 0..31
    const int lkB = (tid & 7) * 4;

    const float* Ab = A + (size_t)lrA * K + lkA;
    const float* Bb = Bw + (size_t)(blockIdx.x * BN + lrB) * K + lkB;

    float acc[4][4];
#pragma unroll
    for (int i = 0; i < 4; i++)
#pragma unroll
        for (int j = 0; j < 4; j++) acc[i][j] = 0.f;

    float4 aR[4], bR;
#pragma unroll
    for (int v = 0; v < 4; v++) aR[v] = *reinterpret_cast<const float4*>(Ab + v * 4);
    bR = *reinterpret_cast<const float4*>(Bb);
#pragma unroll
    for (int v = 0; v < 4; v++)
#pragma unroll
        for (int j = 0; j < 4; j++)
            As[0][lkA + v * 4 + j][lrA] = (&aR[v].x)[j];
#pragma unroll
    for (int j = 0; j < 4; j++) Bs[0][lkB + j][lrB] = (&bR.x)[j];
    __syncthreads();

    const int KT = K / BK;
    for (int kt = 0; kt < KT; kt++) {
        const int p = kt & 1;
        if (kt + 1 < KT) {
#pragma unroll
            for (int v = 0; v < 4; v++)
                aR[v] = *reinterpret_cast<const float4*>(Ab + (kt + 1) * BK + v * 4);
            bR = *reinterpret_cast<const float4*>(Bb + (kt + 1) * BK);
        }
#pragma unroll
        for (int kk = 0; kk < BK; kk++) {
            float a[4], b[4];
            *reinterpret_cast<float4*>(a) = *reinterpret_cast<const float4*>(&As[p][kk][tr * 4]);
            *reinterpret_cast<float4*>(b) = *reinterpret_cast<const float4*>(&Bs[p][kk][tc * 4]);
#pragma unroll
            for (int i = 0; i < 4; i++)
#pragma unroll
                for (int j = 0; j < 4; j++)
                    acc[i][j] = fmaf(a[i], b[j], acc[i][j]);
        }
        if (kt + 1 < KT) {
#pragma unroll
            for (int v = 0; v < 4; v++)
#pragma unroll
                for (int j = 0; j < 4; j++)
                    As[p ^ 1][lkA + v * 4 + j][lrA] = (&aR[v].x)[j];
#pragma unroll
            for (int j = 0; j < 4; j++) Bs[p ^ 1][lkB + j][lrB] = (&bR.x)[j];
        }
        __syncthreads();
    }

    const int colBase = blockIdx.x * BN + tc * 4;
#pragma unroll
    for (int i = 0; i < 4; i++) {
        const int row = tr * 4 + i;
        size_t off = (size_t)row * N + colBase;
        float o[4];
        if (Cin) {
            float4 ci = *reinterpret_cast<const float4*>(&Cin[off]);
#pragma unroll
            for (int j = 0; j < 4; j++) o[j] = acc[i][j] + (&ci.x)[j];
        } else {
#pragma unroll
            for (int j = 0; j < 4; j++) o[j] = acc[i][j];
        }
        *reinterpret_cast<float4*>(&C[off]) = *reinterpret_cast<float4*>(o);
    }
}

// ---------------- helpers -----------------------------------------------
__device__ __forceinline__ float sigm(float x) { return 1.f / (1.f + expf(-x)); }

__global__ void zero_state()
{
    int idx = blockIdx.x * blockDim.x + threadIdx.x;
    if (idx < B_*H_) { d_h1[idx] = 0.f; d_c1[idx] = 0.f; d_c2[idx] = 0.f; }
    if (idx < B_*K2) d_ST[idx] = 0.f;
}

__global__ void pack_hx(const float* __restrict__ Whh1, const float* __restrict__ Wsh,
                        const float* __restrict__ Wih1, const float* __restrict__ Wsi,
                        const float* __restrict__ b1,   const float* __restrict__ bbd)
{
    int i4 = blockIdx.x * blockDim.x + threadIdx.x;   // float4 index
    if (i4 < NA*H_/4) {
        size_t idx = (size_t)i4 * 4;
        const float4* srcH = (idx < (size_t)G4*H_) ? (const float4*)(Whh1 + idx)
                                                   : (const float4*)(Wsh + (idx - (size_t)G4*H_));
        const float4* srcX = (idx < (size_t)G4*H_) ? (const float4*)(Wih1 + idx)
                                                   : (const float4*)(Wsi + (idx - (size_t)G4*H_));
        *reinterpret_cast<float4*>(d_Wh + idx) = *srcH;
        *reinterpret_cast<float4*>(d_Wx + idx) = *srcX;
    }
    if (i4 < NA)
        d_bx[i4] = (i4 < G4) ? b1[i4] : bbd[i4 - G4];
}

__global__ void pack_b(const float* __restrict__ Wih2, const float* __restrict__ Whh2)
{
    size_t i4 = (size_t)blockIdx.x * blockDim.x + threadIdx.x;
    if (i4 >= (size_t)G4*K2/4) return;
    size_t idx = i4 * 4;
    int n = (int)(idx >> 11), k = (int)(idx & (K2 - 1));
    const float4* src = (k < H_) ? (const float4*)(Wih2 + (size_t)n*H_ + k)
                                 : (const float4*)(Whh2 + (size_t)n*H_ + (k - H_));
    *reinterpret_cast<float4*>(d_Wb + idx) = *src;
}

// per-step: boundary gate + LSTM1 activations (one CTA per batch row)
__global__ void act_a(const float* __restrict__ vs)
{
    int b = blockIdx.x;
    int tid = threadIdx.x;
    const float* Yb = d_Y1 + (size_t)b * NA;
    __shared__ float red[256];

    float p = Yb[G4 + tid] * vs[tid] + Yb[G4 + 256 + tid] * vs[256 + tid];
    red[tid] = p;
    __syncthreads();
    for (int off = 128; off > 0; off >>= 1) {
        if (tid < off) red[tid] += red[tid + off];
        __syncthreads();
    }
    float s = rintf(1.f / (1.f + expf(-red[0])));   // round-half-even, matches jnp.round
    if (tid == 0) d_s[b] = s;

    for (int j = tid; j < H_; j += 256) {
        float gi = Yb[j], gf = Yb[H_ + j], gg = Yb[2*H_ + j], go = Yb[3*H_ + j];
        float c = sigm(gf) * d_c1[b*H_ + j] + sigm(gi) * tanhf(gg);
        float h = sigm(go) * tanhf(c);
        d_c1r[b*H_ + j] = c;
        d_h1r[b*H_ + j] = h;
        d_ST[b*K2 + j] = h * s;       // lstm2 input
    }
}

// per-step: LSTM2 activations + state commits
__global__ void act_b(float* __restrict__ out2)
{
    int idx = blockIdx.x * blockDim.x + threadIdx.x;
    if (idx >= B_*H_) return;
    int b = idx >> 10, j = idx & (H_ - 1);
    const float* Yb = d_Y2 + (size_t)b * G4;
    float gi = Yb[j], gf = Yb[H_ + j], gg = Yb[2*H_ + j], go = Yb[3*H_ + j];
    float c = sigm(gf) * d_c2[idx] + sigm(gi) * tanhf(gg);
    float h = sigm(go) * tanhf(c);
    d_c2[idx] = c;
    d_ST[b*K2 + H_ + j] = h;          // h2 for next step's GEMM_B
    out2[idx] = h;
    float s = d_s[b];
    d_h1[idx] = d_h1r[idx] * (1.f - s);
    d_c1[idx] = d_c1r[idx] * (1.f - s);
}

// ---------------- launch -----------------------------------------------
extern "C" void kernel_launch(void* const* d_in, const int* in_sizes, int n_in,
                              void* d_out, int out_size)
{
    const float* video = (const float*)d_in[0];
    const float* Wemb  = (const float*)d_in[1];
    const float* bemb  = (const float*)d_in[2];
    const float* Wih1  = (const float*)d_in[3];
    const float* Whh1  = (const float*)d_in[4];
    const float* b1    = (const float*)d_in[5];
    const float* Wsi   = (const float*)d_in[6];
    const float* Wsh   = (const float*)d_in[7];
    const float* bbd   = (const float*)d_in[8];
    const float* vs    = (const float*)d_in[9];
    const float* Wih2  = (const float*)d_in[10];
    const float* Whh2  = (const float*)d_in[11];

    float *pV, *pGXZ, *pWh, *pWx, *pbx, *pWb, *pY1, *pY2, *ph1, *pST, *pdum;
    cudaGetSymbolAddress((void**)&pV,   d_V);
    cudaGetSymbolAddress((void**)&pGXZ, d_GXZ);
    cudaGetSymbolAddress((void**)&pWh,  d_Wh);
    cudaGetSymbolAddress((void**)&pWx,  d_Wx);
    cudaGetSymbolAddress((void**)&pbx,  d_bx);
    cudaGetSymbolAddress((void**)&pWb,  d_Wb);
    cudaGetSymbolAddress((void**)&pY1,  d_Y1);
    cudaGetSymbolAddress((void**)&pY2,  d_Y2);
    cudaGetSymbolAddress((void**)&ph1,  d_h1);
    cudaGetSymbolAddress((void**)&pST,  d_ST);
    cudaGetSymbolAddress((void**)&pdum, d_dummy);

    // prep: states, packed weights
    zero_state<<<(B_*K2 + 255) / 256, 256>>>();
    pack_hx<<<(NA*H_/4 + 255) / 256, 256>>>(Whh1, Wsh, Wih1, Wsi, b1, bbd);
    pack_b<<<(int)(((size_t)G4*K2/4 + 255) / 256), 256>>>(Wih2, Whh2);

    // V = relu(video @ W_embed^T + b_embed)   [8192,1024], rows b*T+t
    gemm_big<1><<<dim3(H_/128, (B_*T_)/128), 256>>>(video, (size_t)128 * F_, F_,
                                                    Wemb, pV, bemb, F_, H_);
    // GXZ[t*B+b] = V[b*T+t] @ [W_ih1;Wsi]^T + [b1;b_bd]   (strided A, no transpose)
    gemm_big<0><<<dim3(NA/128, (B_*T_)/128), 256>>>(pV, (size_t)H_, T_ * H_,
                                                    pWx, pGXZ, pbx, H_, NA);

    // sequential scan over T
    for (int t = 0; t < T_; t++) {
        // Y1 = h1 @ [W_hh1;Wsh]^T + GXZ[t]
        gemm_seq<<<NA/32, 256>>>(ph1, pWh, pY1, pGXZ + (size_t)t * B_ * NA, H_, NA);
        act_a<<<B_, 256>>>(vs);
        // Y2 = [h1raw*s | h2] @ [W_ih2 | W_hh2]^T   (K = 2048)
        gemm_seq<<<G4/32, 256>>>(pST, pWb, pY2, nullptr, K2, G4);
        act_b<<<(B_*H_ + 255) / 256, 256>>>(t == T_-1 ? (float*)d_out : pdum);
    }
}

// round 6
// speedup vs baseline: 1.5824x; 1.0933x over previous
#include <cuda_runtime.h>
#include <cuda_fp16.h>
#include <math.h>
#include <stdint.h>

#define B_  128
#define T_  64
#define F_  2048
#define H_  1024
#define M_  512
#define G4  4096   // 4*H
#define NA  4608   // 4H + M
#define K2  2048   // 2H

// ---------------- device scratch (no allocations allowed) -------------------
// fp16 hi/lo splits, plain row-major [rows][K]
__device__ __align__(128) __half d_VidH[(size_t)B_*T_*F_];
__device__ __align__(128) __half d_VidL[(size_t)B_*T_*F_];
__device__ __align__(128) __half d_WembH[(size_t)H_*F_];
__device__ __align__(128) __half d_WembL[(size_t)H_*F_];
__device__ __align__(128) __half d_VH[(size_t)B_*T_*H_];     // relu(embed) split, rows b*T+t
__device__ __align__(128) __half d_VL[(size_t)B_*T_*H_];
__device__ __align__(128) __half d_WxH[(size_t)NA*H_];       // [W_ih1; Wsi]
__device__ __align__(128) __half d_WxL[(size_t)NA*H_];
__device__ __align__(128) __half d_WhH[(size_t)NA*H_];       // [W_hh1; Wsh]
__device__ __align__(128) __half d_WhL[(size_t)NA*H_];
__device__ __align__(128) __half d_WbH[(size_t)G4*K2];       // [W_ih2 | W_hh2]
__device__ __align__(128) __half d_WbL[(size_t)G4*K2];
__device__ __align__(128) __half d_AhH[B_*H_];               // h1 split (Y1 A)
__device__ __align__(128) __half d_AhL[B_*H_];
__device__ __align__(128) __half d_STH[B_*K2];               // [h1r*s | h2] (Y2 A)
__device__ __align__(128) __half d_STL[B_*K2];

__device__ float d_bx [NA];                  // [b1; b_bd]
__device__ float d_GXZ[(size_t)B_*T_*NA];    // rows t*B+b
__device__ float d_Y1 [B_*NA];
__device__ float d_Y2 [B_*G4];
__device__ float d_c1 [B_*H_];
__device__ float d_c2 [B_*H_];
__device__ float d_h1r[B_*H_];
__device__ float d_c1r[B_*H_];
__device__ float d_s  [B_];
__device__ float d_dummy[B_*H_];

// ---------------- asm helpers ------------------------------------------------
__device__ __forceinline__ uint32_t s2u_(const void* p) {
    uint32_t a;
    asm("{ .reg .u64 t; cvta.to.shared.u64 t, %1; cvt.u32.u64 %0, t; }" : "=r"(a) : "l"(p));
    return a;
}
__device__ __forceinline__ void cp16_(uint32_t d, const void* s) {
    asm volatile("cp.async.cg.shared.global [%0], [%1], 16;" :: "r"(d), "l"(s));
}
__device__ __forceinline__ void ldsm4_(uint32_t a, uint32_t& r0, uint32_t& r1, uint32_t& r2, uint32_t& r3) {
    asm volatile("ldmatrix.sync.aligned.m8n8.x4.shared.b16 {%0,%1,%2,%3}, [%4];"
                 : "=r"(r0), "=r"(r1), "=r"(r2), "=r"(r3) : "r"(a));
}
__device__ __forceinline__ void hmma_(float* c, const uint32_t* a, const uint32_t* b) {
    asm volatile("mma.sync.aligned.m16n8k16.row.col.f32.f16.f16.f32 "
                 "{%0,%1,%2,%3}, {%4,%5,%6,%7}, {%8,%9}, {%0,%1,%2,%3};"
                 : "+f"(c[0]), "+f"(c[1]), "+f"(c[2]), "+f"(c[3])
                 : "r"(a[0]), "r"(a[1]), "r"(a[2]), "r"(a[3]), "r"(b[0]), "r"(b[1]));
}

// ---------------- HMMA GEMM --------------------------------------------------
// C[64*by + r, 128*bx + c] = sum_k A[r,k]*B[n,k]  with A,B given as fp16 hi/lo
// pairs; computes HH + HL + LH (3-pass, ~fp32 precision).
// A tile offset = (by&1)*aS1 + (by>>1)*aS2 (affine trick covers strided row maps).
// smem stage: AH[64][40] AL[64][40] BH[128][40] BL[128][40] halfs (80B rows).
constexpr int STAGE_B = 30720;                 // bytes per stage
constexpr int SMEM_TOT = 2 * STAGE_B;          // 61440
constexpr int OB_B = 10240;                    // B region byte offset in stage

template<int HAS_CIN, int HAS_BIAS, int RELU, int SPLIT_OUT>
__global__ __launch_bounds__(256)
void gemm_h(const __half* __restrict__ AH, const __half* __restrict__ AL,
            size_t aS1, size_t aS2, int lda,
            const __half* __restrict__ BH, const __half* __restrict__ BL,
            float* __restrict__ C, const float* __restrict__ Cin, int ldcin,
            const float* __restrict__ bias,
            __half* __restrict__ OH, __half* __restrict__ OL,
            int K, int N)
{
    extern __shared__ __align__(128) char sm[];
    const uint32_t sb = s2u_(sm);
    const int tid  = threadIdx.x;
    const int lane = tid & 31;
    const int wid  = tid >> 5;
    const int wm   = wid & 1;          // 2 warps along M (32 rows each)
    const int wn   = wid >> 1;         // 4 warps along N (32 cols each)
    const int bx   = blockIdx.x, by = blockIdx.y;

    const size_t aOff = (size_t)(by & 1) * aS1 + (size_t)(by >> 1) * aS2;
    const __half* gAH = AH + aOff;
    const __half* gAL = AL + aOff;
    const __half* gBH = BH + (size_t)bx * 128 * K;
    const __half* gBL = BL + (size_t)bx * 128 * K;

    float acc[2][4][4];
#pragma unroll
    for (int i = 0; i < 2; i++)
#pragma unroll
        for (int j = 0; j < 4; j++)
#pragma unroll
            for (int q = 0; q < 4; q++) acc[i][j][q] = 0.f;

    auto load_stage = [&](int p, int kt) {
        const uint32_t dst = sb + p * STAGE_B;
        const int k0 = kt * 32;
#pragma unroll
        for (int i = 0; i < 2; i++) {                 // A: 512 chunks
            int c = tid * 2 + i;
            int row = c >> 2, col = c & 3;
            const __half* src = (row < 64) ? (gAH + (size_t)row * lda)
                                           : (gAL + (size_t)(row - 64) * lda);
            cp16_(dst + row * 80 + col * 16, src + k0 + col * 8);
        }
#pragma unroll
        for (int i = 0; i < 4; i++) {                 // B: 1024 chunks
            int c = tid * 4 + i;
            int row = c >> 2, col = c & 3;
            const __half* src = (row < 128) ? (gBH + (size_t)row * K)
                                            : (gBL + (size_t)(row - 128) * K);
            cp16_(dst + OB_B + row * 80 + col * 16, src + k0 + col * 8);
        }
        asm volatile("cp.async.commit_group;" ::: "memory");
    };

    const int KT = K / 32;
    load_stage(0, 0);

    const int rsel = lane & 15, csel = lane >> 4;

    for (int kt = 0; kt < KT; kt++) {
        const int p = kt & 1;
        if (kt + 1 < KT) {
            load_stage(p ^ 1, kt + 1);
            asm volatile("cp.async.wait_group 1;" ::: "memory");
        } else {
            asm volatile("cp.async.wait_group 0;" ::: "memory");
        }
        __syncthreads();

        const uint32_t stg = sb + p * STAGE_B;
#pragma unroll
        for (int h = 0; h < 2; h++) {
            uint32_t aH[2][4], aL[2][4], bHf[4][2], bLf[4][2];
#pragma unroll
            for (int mi = 0; mi < 2; mi++) {
                int row = wm * 32 + mi * 16 + rsel;
                uint32_t ad = stg + row * 80 + h * 32 + csel * 16;
                ldsm4_(ad,        aH[mi][0], aH[mi][1], aH[mi][2], aH[mi][3]);
                ldsm4_(ad + 5120, aL[mi][0], aL[mi][1], aL[mi][2], aL[mi][3]);
            }
#pragma unroll
            for (int g = 0; g < 2; g++) {
                int row = wn * 32 + g * 16 + rsel;
                uint32_t bd = stg + OB_B + row * 80 + h * 32 + csel * 16;
                uint32_t t0, t1, t2, t3;
                ldsm4_(bd, t0, t1, t2, t3);
                bHf[g*2][0] = t0; bHf[g*2][1] = t2; bHf[g*2+1][0] = t1; bHf[g*2+1][1] = t3;
                ldsm4_(bd + 10240, t0, t1, t2, t3);
                bLf[g*2][0] = t0; bLf[g*2][1] = t2; bLf[g*2+1][0] = t1; bLf[g*2+1][1] = t3;
            }
#pragma unroll
            for (int mi = 0; mi < 2; mi++)
#pragma unroll
                for (int ni = 0; ni < 4; ni++) {
                    hmma_(acc[mi][ni], aH[mi], bHf[ni]);   // HH
                    hmma_(acc[mi][ni], aH[mi], bLf[ni]);   // HL
                    hmma_(acc[mi][ni], aL[mi], bHf[ni]);   // LH
                }
        }
        __syncthreads();
    }

    // epilogue
#pragma unroll
    for (int mi = 0; mi < 2; mi++)
#pragma unroll
        for (int ni = 0; ni < 4; ni++) {
            const int row0 = by * 64 + wm * 32 + mi * 16 + (lane >> 2);
            const int col  = bx * 128 + wn * 32 + ni * 8 + (lane & 3) * 2;
            float v[4];
#pragma unroll
            for (int q = 0; q < 4; q++) v[q] = acc[mi][ni][q];
            if (HAS_BIAS) {
                float b0 = bias[col], b1 = bias[col + 1];
                v[0] += b0; v[1] += b1; v[2] += b0; v[3] += b1;
            }
            if (HAS_CIN) {
                float2 c0 = *reinterpret_cast<const float2*>(&Cin[(size_t)row0 * ldcin + col]);
                float2 c1 = *reinterpret_cast<const float2*>(&Cin[(size_t)(row0 + 8) * ldcin + col]);
                v[0] += c0.x; v[1] += c0.y; v[2] += c1.x; v[3] += c1.y;
            }
            if (RELU) {
#pragma unroll
                for (int q = 0; q < 4; q++) v[q] = fmaxf(v[q], 0.f);
            }
            if (SPLIT_OUT) {
#pragma unroll
                for (int q = 0; q < 4; q++) {
                    int r = row0 + (q >> 1) * 8, c = col + (q & 1);
                    __half hi = __float2half(v[q]);
                    __half lo = __float2half(v[q] - __half2float(hi));
                    OH[(size_t)r * N + c] = hi;
                    OL[(size_t)r * N + c] = lo;
                }
            } else {
                *reinterpret_cast<float2*>(&C[(size_t)row0 * N + col])       = make_float2(v[0], v[1]);
                *reinterpret_cast<float2*>(&C[(size_t)(row0 + 8) * N + col]) = make_float2(v[2], v[3]);
            }
        }
}

// ---------------- split / pack kernels --------------------------------------
// mode 0: rows [S1(G4 rows); S2]. mode 1: cols [S1 | S2] each H_ wide. mode 2: plain.
__global__ void split_w(const float* __restrict__ S1, const float* __restrict__ S2,
                        __half* __restrict__ Hh, __half* __restrict__ Ll,
                        int KSHIFT, int mode, size_t total)
{
    size_t idx = (size_t)blockIdx.x * blockDim.x + threadIdx.x;
    if (idx >= total) return;
    const int K = 1 << KSHIFT;
    const int n = (int)(idx >> KSHIFT);
    const int k = (int)(idx & (K - 1));
    float v;
    if (mode == 0)      v = (n < G4) ? S1[idx] : S2[idx - (size_t)G4 * K];
    else if (mode == 1) v = (k < H_) ? S1[((size_t)n << 10) + k] : S2[((size_t)n << 10) + k - H_];
    else                v = S1[idx];
    __half hi = __float2half(v);
    __half lo = __float2half(v - __half2float(hi));
    Hh[idx] = hi; Ll[idx] = lo;
}

__global__ void pack_bias(const float* __restrict__ b1, const float* __restrict__ bbd)
{
    int i = blockIdx.x * blockDim.x + threadIdx.x;
    if (i < NA) d_bx[i] = (i < G4) ? b1[i] : bbd[i - G4];
}

__global__ void zero_state()
{
    int i = blockIdx.x * blockDim.x + threadIdx.x;
    __half z = __float2half(0.f);
    if (i < B_ * H_) { d_c1[i] = 0.f; d_c2[i] = 0.f; d_AhH[i] = z; d_AhL[i] = z; }
    if (i < B_ * K2) { d_STH[i] = z; d_STL[i] = z; }
}

// ---------------- activations -----------------------------------------------
__device__ __forceinline__ float sigm(float x) { return 1.f / (1.f + expf(-x)); }

__global__ void act_a(const float* __restrict__ vs)
{
    int b = blockIdx.x, tid = threadIdx.x;
    const float* Yb = d_Y1 + (size_t)b * NA;
    __shared__ float red[256];
    float p = Yb[G4 + tid] * vs[tid] + Yb[G4 + 256 + tid] * vs[256 + tid];
    red[tid] = p;
    __syncthreads();
    for (int off = 128; off > 0; off >>= 1) {
        if (tid < off) red[tid] += red[tid + off];
        __syncthreads();
    }
    float s = rintf(1.f / (1.f + expf(-red[0])));   // half-even, matches jnp.round
    if (tid == 0) d_s[b] = s;

    for (int j = tid; j < H_; j += 256) {
        float gi = Yb[j], gf = Yb[H_ + j], gg = Yb[2 * H_ + j], go = Yb[3 * H_ + j];
        float c = sigm(gf) * d_c1[b * H_ + j] + sigm(gi) * tanhf(gg);
        float h = sigm(go) * tanhf(c);
        d_c1r[b * H_ + j] = c;
        d_h1r[b * H_ + j] = h;
        float v = h * s;                            // lstm2 input, cols [0,1024)
        __half hi = __float2half(v);
        __half lo = __float2half(v - __half2float(hi));
        d_STH[b * K2 + j] = hi;
        d_STL[b * K2 + j] = lo;
    }
}

__global__ void act_b(float* __restrict__ out2)
{
    int idx = blockIdx.x * blockDim.x + threadIdx.x;
    if (idx >= B_ * H_) return;
    int b = idx >> 10, j = idx & (H_ - 1);
    const float* Yb = d_Y2 + (size_t)b * G4;
    float gi = Yb[j], gf = Yb[H_ + j], gg = Yb[2 * H_ + j], go = Yb[3 * H_ + j];
    float c = sigm(gf) * d_c2[idx] + sigm(gi) * tanhf(gg);
    float h = sigm(go) * tanhf(c);
    d_c2[idx] = c;
    out2[idx] = h;
    {   // h2 -> ST cols [1024,2048)
        __half hi = __float2half(h);
        __half lo = __float2half(h - __half2float(hi));
        d_STH[b * K2 + H_ + j] = hi;
        d_STL[b * K2 + H_ + j] = lo;
    }
    float s = d_s[b];
    float h1 = d_h1r[idx] * (1.f - s);
    d_c1[idx] = d_c1r[idx] * (1.f - s);
    {   // h1 -> Y1 A operand
        __half hi = __float2half(h1);
        __half lo = __float2half(h1 - __half2float(hi));
        d_AhH[idx] = hi;
        d_AhL[idx] = lo;
    }
}

// ---------------- launch -----------------------------------------------------
extern "C" void kernel_launch(void* const* d_in, const int* in_sizes, int n_in,
                              void* d_out, int out_size)
{
    const float* video = (const float*)d_in[0];
    const float* Wemb  = (const float*)d_in[1];
    const float* bemb  = (const float*)d_in[2];
    const float* Wih1  = (const float*)d_in[3];
    const float* Whh1  = (const float*)d_in[4];
    const float* b1    = (const float*)d_in[5];
    const float* Wsi   = (const float*)d_in[6];
    const float* Wsh   = (const float*)d_in[7];
    const float* bbd   = (const float*)d_in[8];
    const float* vs    = (const float*)d_in[9];
    const float* Wih2  = (const float*)d_in[10];
    const float* Whh2  = (const float*)d_in[11];

    __half *pVidH,*pVidL,*pWembH,*pWembL,*pVH,*pVL,*pWxH,*pWxL,*pWhH,*pWhL,*pWbH,*pWbL,*pAhH,*pAhL,*pSTH,*pSTL;
    float *pbx,*pGXZ,*pY1,*pY2,*pdum;
    cudaGetSymbolAddress((void**)&pVidH, d_VidH);  cudaGetSymbolAddress((void**)&pVidL, d_VidL);
    cudaGetSymbolAddress((void**)&pWembH,d_WembH); cudaGetSymbolAddress((void**)&pWembL,d_WembL);
    cudaGetSymbolAddress((void**)&pVH,   d_VH);    cudaGetSymbolAddress((void**)&pVL,   d_VL);
    cudaGetSymbolAddress((void**)&pWxH,  d_WxH);   cudaGetSymbolAddress((void**)&pWxL,  d_WxL);
    cudaGetSymbolAddress((void**)&pWhH,  d_WhH);   cudaGetSymbolAddress((void**)&pWhL,  d_WhL);
    cudaGetSymbolAddress((void**)&pWbH,  d_WbH);   cudaGetSymbolAddress((void**)&pWbL,  d_WbL);
    cudaGetSymbolAddress((void**)&pAhH,  d_AhH);   cudaGetSymbolAddress((void**)&pAhL,  d_AhL);
    cudaGetSymbolAddress((void**)&pSTH,  d_STH);   cudaGetSymbolAddress((void**)&pSTL,  d_STL);
    cudaGetSymbolAddress((void**)&pbx,   d_bx);
    cudaGetSymbolAddress((void**)&pGXZ,  d_GXZ);
    cudaGetSymbolAddress((void**)&pY1,   d_Y1);
    cudaGetSymbolAddress((void**)&pY2,   d_Y2);
    cudaGetSymbolAddress((void**)&pdum,  d_dummy);

    cudaFuncSetAttribute(gemm_h<0,1,1,1>, cudaFuncAttributeMaxDynamicSharedMemorySize, SMEM_TOT);
    cudaFuncSetAttribute(gemm_h<0,1,0,0>, cudaFuncAttributeMaxDynamicSharedMemorySize, SMEM_TOT);
    cudaFuncSetAttribute(gemm_h<1,0,0,0>, cudaFuncAttributeMaxDynamicSharedMemorySize, SMEM_TOT);
    cudaFuncSetAttribute(gemm_h<0,0,0,0>, cudaFuncAttributeMaxDynamicSharedMemorySize, SMEM_TOT);

    zero_state<<<(B_*K2 + 255) / 256, 256>>>();
    pack_bias<<<(NA + 255) / 256, 256>>>(b1, bbd);
    {
        size_t n;
        n = (size_t)H_ * F_;   split_w<<<(int)((n + 255) / 256), 256>>>(Wemb,  nullptr, pWembH, pWembL, 11, 2, n);
        n = (size_t)NA * H_;   split_w<<<(int)((n + 255) / 256), 256>>>(Wih1,  Wsi,     pWxH,   pWxL,   10, 0, n);
        n = (size_t)NA * H_;   split_w<<<(int)((n + 255) / 256), 256>>>(Whh1,  Wsh,     pWhH,   pWhL,   10, 0, n);
        n = (size_t)G4 * K2;   split_w<<<(int)((n + 255) / 256), 256>>>(Wih2,  Whh2,    pWbH,   pWbL,   11, 1, n);
        n = (size_t)B_*T_*F_;  split_w<<<(int)((n + 255) / 256), 256>>>(video, nullptr, pVidH,  pVidL,  11, 2, n);
    }

    // V = relu(video @ Wemb^T + bemb) -> fp16 split (rows b*T+t)
    gemm_h<0,1,1,1><<<dim3(H_/128, (B_*T_)/64), 256, SMEM_TOT>>>(
        pVidH, pVidL, (size_t)64 * F_, (size_t)128 * F_, F_,
        pWembH, pWembL, nullptr, nullptr, 0, bemb, pVH, pVL, F_, H_);
    // GXZ[t*B+b] = V[b*T+t] @ [Wih1;Wsi]^T + [b1;b_bd]
    // A row stride (consecutive b at fixed t) = T_*H_;  tile offsets: 64 b-rows = 64*T_*H_, t-step = H_
    gemm_h<0,1,0,0><<<dim3(NA/128, (B_*T_)/64), 256, SMEM_TOT>>>(
        pVH, pVL, (size_t)64 * T_ * H_, (size_t)H_, T_ * H_,
        pWxH, pWxL, pGXZ, nullptr, 0, pbx, nullptr, nullptr, H_, NA);

    for (int t = 0; t < T_; t++) {
        // Y1 = h1 @ [Whh1;Wsh]^T + GXZ[t]
        gemm_h<1,0,0,0><<<dim3(NA/128, 2), 256, SMEM_TOT>>>(
            pAhH, pAhL, (size_t)64 * H_, 0, H_,
            pWhH, pWhL, pY1, pGXZ + (size_t)t * B_ * NA, NA, nullptr, nullptr, nullptr, H_, NA);
        act_a<<<B_, 256>>>(vs);
        // Y2 = [h1r*s | h2] @ [Wih2 | Whh2]^T
        gemm_h<0,0,0,0><<<dim3(G4/128, 2), 256, SMEM_TOT>>>(
            pSTH, pSTL, (size_t)64 * K2, 0, K2,
            pWbH, pWbL, pY2, nullptr, 0, nullptr, nullptr, nullptr, K2, G4);
        act_b<<<(B_*H_ + 255) / 256, 256>>>(t == T_ - 1 ? (float*)d_out : pdum);
    }
}

// round 7
// speedup vs baseline: 1.6082x; 1.0163x over previous
#include <cuda_runtime.h>
#include <cuda_fp16.h>
#include <math.h>
#include <stdint.h>

#define B_  128
#define T_  64
#define F_  2048
#define H_  1024
#define M_  512
#define G4  4096   // 4*H
#define NA  4608   // 4H + M
#define K2  2048   // 2H
#define NCTA 148

// ---------------- device scratch (no allocations allowed) -------------------
__device__ __align__(128) __half d_VidH[(size_t)B_*T_*F_];
__device__ __align__(128) __half d_VidL[(size_t)B_*T_*F_];
__device__ __align__(128) __half d_WembH[(size_t)H_*F_];
__device__ __align__(128) __half d_WembL[(size_t)H_*F_];
__device__ __align__(128) __half d_VH[(size_t)B_*T_*H_];     // relu(embed) split, rows b*T+t
__device__ __align__(128) __half d_VL[(size_t)B_*T_*H_];
__device__ __align__(128) __half d_WxH[(size_t)NA*H_];       // [W_ih1; Wsi]
__device__ __align__(128) __half d_WxL[(size_t)NA*H_];
__device__ __align__(128) __half d_WhH[(size_t)NA*H_];       // [W_hh1; Wsh]
__device__ __align__(128) __half d_WhL[(size_t)NA*H_];
__device__ __align__(128) __half d_WbH[(size_t)G4*K2];       // [W_ih2 | W_hh2]
__device__ __align__(128) __half d_WbL[(size_t)G4*K2];
__device__ __align__(128) __half d_AhH[B_*H_];               // h1 split (Y1 A)
__device__ __align__(128) __half d_AhL[B_*H_];
__device__ __align__(128) __half d_STH[B_*K2];               // [h1r*s | h2] (Y2 A)
__device__ __align__(128) __half d_STL[B_*K2];

__device__ float d_bx [NA];                  // [b1; b_bd]
__device__ float d_GXZ[(size_t)B_*T_*NA];    // rows t*B+b
__device__ float d_Y1 [B_*NA];
__device__ float d_Y2 [B_*G4];
__device__ float d_c1 [B_*H_];
__device__ float d_c2 [B_*H_];
__device__ float d_h1r[B_*H_];
__device__ float d_c1r[B_*H_];
__device__ float d_s  [B_];
__device__ unsigned int d_bars[260];

// ---------------- asm helpers ------------------------------------------------
__device__ __forceinline__ uint32_t s2u_(const void* p) {
    uint32_t a;
    asm("{ .reg .u64 t; cvta.to.shared.u64 t, %1; cvt.u32.u64 %0, t; }" : "=r"(a) : "l"(p));
    return a;
}
__device__ __forceinline__ void cp16_(uint32_t d, const void* s) {
    asm volatile("cp.async.cg.shared.global [%0], [%1], 16;" :: "r"(d), "l"(s));
}
__device__ __forceinline__ void ldsm4_(uint32_t a, uint32_t& r0, uint32_t& r1, uint32_t& r2, uint32_t& r3) {
    asm volatile("ldmatrix.sync.aligned.m8n8.x4.shared.b16 {%0,%1,%2,%3}, [%4];"
                 : "=r"(r0), "=r"(r1), "=r"(r2), "=r"(r3) : "r"(a));
}
__device__ __forceinline__ void hmma_(float* c, const uint32_t* a, const uint32_t* b) {
    asm volatile("mma.sync.aligned.m16n8k16.row.col.f32.f16.f16.f32 "
                 "{%0,%1,%2,%3}, {%4,%5,%6,%7}, {%8,%9}, {%0,%1,%2,%3};"
                 : "+f"(c[0]), "+f"(c[1]), "+f"(c[2]), "+f"(c[3])
                 : "r"(a[0]), "r"(a[1]), "r"(a[2]), "r"(a[3]), "r"(b[0]), "r"(b[1]));
}
__device__ __forceinline__ float sigm(float x) { return 1.f / (1.f + expf(-x)); }

// ---------------- precompute HMMA GEMM (64x128 tiles, as R6) -----------------
constexpr int STAGE_B = 30720;
constexpr int SMEM_TOT = 2 * STAGE_B;
constexpr int OB_B = 10240;

template<int HAS_BIAS, int RELU, int SPLIT_OUT>
__global__ __launch_bounds__(256)
void gemm_h(const __half* __restrict__ AH, const __half* __restrict__ AL,
            size_t aS1, size_t aS2, int lda,
            const __half* __restrict__ BH, const __half* __restrict__ BL,
            float* __restrict__ C,
            const float* __restrict__ bias,
            __half* __restrict__ OH, __half* __restrict__ OL,
            int K, int N)
{
    extern __shared__ __align__(128) char sm[];
    const uint32_t sb = s2u_(sm);
    const int tid  = threadIdx.x;
    const int lane = tid & 31;
    const int wid  = tid >> 5;
    const int wm   = wid & 1;
    const int wn   = wid >> 1;
    const int bx   = blockIdx.x, by = blockIdx.y;

    const size_t aOff = (size_t)(by & 1) * aS1 + (size_t)(by >> 1) * aS2;
    const __half* gAH = AH + aOff;
    const __half* gAL = AL + aOff;
    const __half* gBH = BH + (size_t)bx * 128 * K;
    const __half* gBL = BL + (size_t)bx * 128 * K;

    float acc[2][4][4];
#pragma unroll
    for (int i = 0; i < 2; i++)
#pragma unroll
        for (int j = 0; j < 4; j++)
#pragma unroll
            for (int q = 0; q < 4; q++) acc[i][j][q] = 0.f;

    auto load_stage = [&](int p, int kt) {
        const uint32_t dst = sb + p * STAGE_B;
        const int k0 = kt * 32;
#pragma unroll
        for (int i = 0; i < 2; i++) {
            int c = tid * 2 + i;
            int row = c >> 2, col = c & 3;
            const __half* src = (row < 64) ? (gAH + (size_t)row * lda)
                                           : (gAL + (size_t)(row - 64) * lda);
            cp16_(dst + row * 80 + col * 16, src + k0 + col * 8);
        }
#pragma unroll
        for (int i = 0; i < 4; i++) {
            int c = tid * 4 + i;
            int row = c >> 2, col = c & 3;
            const __half* src = (row < 128) ? (gBH + (size_t)row * K)
                                            : (gBL + (size_t)(row - 128) * K);
            cp16_(dst + OB_B + row * 80 + col * 16, src + k0 + col * 8);
        }
        asm volatile("cp.async.commit_group;" ::: "memory");
    };

    const int KT = K / 32;
    load_stage(0, 0);
    const int rsel = lane & 15, csel = lane >> 4;

    for (int kt = 0; kt < KT; kt++) {
        const int p = kt & 1;
        if (kt + 1 < KT) {
            load_stage(p ^ 1, kt + 1);
            asm volatile("cp.async.wait_group 1;" ::: "memory");
        } else {
            asm volatile("cp.async.wait_group 0;" ::: "memory");
        }
        __syncthreads();
        const uint32_t stg = sb + p * STAGE_B;
#pragma unroll
        for (int h = 0; h < 2; h++) {
            uint32_t aH[2][4], aL[2][4], bHf[4][2], bLf[4][2];
#pragma unroll
            for (int mi = 0; mi < 2; mi++) {
                int row = wm * 32 + mi * 16 + rsel;
                uint32_t ad = stg + row * 80 + h * 32 + csel * 16;
                ldsm4_(ad,        aH[mi][0], aH[mi][1], aH[mi][2], aH[mi][3]);
                ldsm4_(ad + 5120, aL[mi][0], aL[mi][1], aL[mi][2], aL[mi][3]);
            }
#pragma unroll
            for (int g = 0; g < 2; g++) {
                int row = wn * 32 + g * 16 + rsel;
                uint32_t bd = stg + OB_B + row * 80 + h * 32 + csel * 16;
                uint32_t t0, t1, t2, t3;
                ldsm4_(bd, t0, t1, t2, t3);
                bHf[g*2][0] = t0; bHf[g*2][1] = t2; bHf[g*2+1][0] = t1; bHf[g*2+1][1] = t3;
                ldsm4_(bd + 10240, t0, t1, t2, t3);
                bLf[g*2][0] = t0; bLf[g*2][1] = t2; bLf[g*2+1][0] = t1; bLf[g*2+1][1] = t3;
            }
#pragma unroll
            for (int mi = 0; mi < 2; mi++)
#pragma unroll
                for (int ni = 0; ni < 4; ni++) {
                    hmma_(acc[mi][ni], aH[mi], bHf[ni]);
                    hmma_(acc[mi][ni], aH[mi], bLf[ni]);
                    hmma_(acc[mi][ni], aL[mi], bHf[ni]);
                }
        }
        __syncthreads();
    }

#pragma unroll
    for (int mi = 0; mi < 2; mi++)
#pragma unroll
        for (int ni = 0; ni < 4; ni++) {
            const int row0 = by * 64 + wm * 32 + mi * 16 + (lane >> 2);
            const int col  = bx * 128 + wn * 32 + ni * 8 + (lane & 3) * 2;
            float v[4];
#pragma unroll
            for (int q = 0; q < 4; q++) v[q] = acc[mi][ni][q];
            if (HAS_BIAS) {
                float b0 = bias[col], b1 = bias[col + 1];
                v[0] += b0; v[1] += b1; v[2] += b0; v[3] += b1;
            }
            if (RELU) {
#pragma unroll
                for (int q = 0; q < 4; q++) v[q] = fmaxf(v[q], 0.f);
            }
            if (SPLIT_OUT) {
#pragma unroll
                for (int q = 0; q < 4; q++) {
                    int r = row0 + (q >> 1) * 8, c = col + (q & 1);
                    __half hi = __float2half(v[q]);
                    __half lo = __float2half(v[q] - __half2float(hi));
                    OH[(size_t)r * N + c] = hi;
                    OL[(size_t)r * N + c] = lo;
                }
            } else {
                *reinterpret_cast<float2*>(&C[(size_t)row0 * N + col])       = make_float2(v[0], v[1]);
                *reinterpret_cast<float2*>(&C[(size_t)(row0 + 8) * N + col]) = make_float2(v[2], v[3]);
            }
        }
}

// ---------------- persistent scan kernel ------------------------------------
// 64x64 tile GEMM helper (8 warps: 2 along M x 4 along N, warp 32x16)
__device__ __forceinline__ void tile_mm(
    const __half* __restrict__ AH, const __half* __restrict__ AL, int lda,
    const __half* __restrict__ BH, const __half* __restrict__ BL, int ldb,
    int KT, uint32_t sbase, float acc[2][2][4],
    int tid, int wm, int wn, int rsel, int csel)
{
    auto load_stage = [&](int p, int kt) {
        const uint32_t dst = sbase + p * 20480;
        const int k0 = kt * 32;
#pragma unroll
        for (int i = 0; i < 2; i++) {               // A: 512 chunks of 16B
            int c = tid * 2 + i;
            int row = c >> 2, col = c & 3;
            const __half* src = (row < 64) ? AH + (size_t)row * lda
                                           : AL + (size_t)(row - 64) * lda;
            cp16_(dst + row * 80 + col * 16, src + k0 + col * 8);
        }
#pragma unroll
        for (int i = 0; i < 2; i++) {               // B: 512 chunks
            int c = tid * 2 + i;
            int row = c >> 2, col = c & 3;
            const __half* src = (row < 64) ? BH + (size_t)row * ldb
                                           : BL + (size_t)(row - 64) * ldb;
            cp16_(dst + 10240 + row * 80 + col * 16, src + k0 + col * 8);
        }
        asm volatile("cp.async.commit_group;" ::: "memory");
    };

    load_stage(0, 0);
    for (int kt = 0; kt < KT; kt++) {
        const int p = kt & 1;
        if (kt + 1 < KT) {
            load_stage(p ^ 1, kt + 1);
            asm volatile("cp.async.wait_group 1;" ::: "memory");
        } else {
            asm volatile("cp.async.wait_group 0;" ::: "memory");
        }
        __syncthreads();
        const uint32_t stg = sbase + p * 20480;
#pragma unroll
        for (int h = 0; h < 2; h++) {
            uint32_t aH[2][4], aL[2][4], bH[2][2], bL[2][2];
#pragma unroll
            for (int mi = 0; mi < 2; mi++) {
                uint32_t ad = stg + (wm * 32 + mi * 16 + rsel) * 80 + h * 32 + csel * 16;
                ldsm4_(ad,        aH[mi][0], aH[mi][1], aH[mi][2], aH[mi][3]);
                ldsm4_(ad + 5120, aL[mi][0], aL[mi][1], aL[mi][2], aL[mi][3]);
            }
            {
                uint32_t bd = stg + 10240 + (wn * 16 + rsel) * 80 + h * 32 + csel * 16;
                uint32_t t0, t1, t2, t3;
                ldsm4_(bd, t0, t1, t2, t3);
                bH[0][0] = t0; bH[0][1] = t2; bH[1][0] = t1; bH[1][1] = t3;
                ldsm4_(bd + 5120, t0, t1, t2, t3);
                bL[0][0] = t0; bL[0][1] = t2; bL[1][0] = t1; bL[1][1] = t3;
            }
#pragma unroll
            for (int mi = 0; mi < 2; mi++)
#pragma unroll
                for (int ni = 0; ni < 2; ni++) {
                    hmma_(acc[mi][ni], aH[mi], bH[ni]);
                    hmma_(acc[mi][ni], aH[mi], bL[ni]);
                    hmma_(acc[mi][ni], aL[mi], bH[ni]);
                }
        }
        __syncthreads();
    }
}

__global__ __launch_bounds__(256)
void scan_persist(const float* __restrict__ vs, float* __restrict__ out)
{
    __shared__ __align__(128) __half stage[2][10240];
    __shared__ float red[256];
    const uint32_t sbase = s2u_(&stage[0][0]);
    const int tid  = threadIdx.x;
    const int lane = tid & 31;
    const int wid  = tid >> 5;
    const int wm   = wid & 1, wn = wid >> 1;
    const int rsel = lane & 15, csel = lane >> 4;
    const int cta  = blockIdx.x;
    int bar = 0;

    auto gbar = [&]() {
        __threadfence();
        __syncthreads();
        if (tid == 0) {
            atomicAdd(&d_bars[bar], 1u);
            while (*((volatile unsigned int*)&d_bars[bar]) < (unsigned)NCTA) { }
        }
        bar++;
        __syncthreads();
        __threadfence();
    };

    for (int t = 0; t < T_; t++) {
        // -------- P1: Y1 = h1 @ [Whh1;Wsh]^T + GXZ[t]  (144 tiles of 64x64)
        if (cta < 144) {
            const int m = cta / 72, n = cta % 72;
            float acc[2][2][4];
#pragma unroll
            for (int i = 0; i < 2; i++)
#pragma unroll
                for (int j = 0; j < 2; j++)
#pragma unroll
                    for (int q = 0; q < 4; q++) acc[i][j][q] = 0.f;
            tile_mm(d_AhH + (size_t)(m * 64) * H_, d_AhL + (size_t)(m * 64) * H_, H_,
                    d_WhH + (size_t)(n * 64) * H_, d_WhL + (size_t)(n * 64) * H_, H_,
                    H_ / 32, sbase, acc, tid, wm, wn, rsel, csel);
            const float* gx = d_GXZ + (size_t)t * B_ * NA;
#pragma unroll
            for (int mi = 0; mi < 2; mi++)
#pragma unroll
                for (int ni = 0; ni < 2; ni++) {
                    const int r0 = m * 64 + wm * 32 + mi * 16 + (lane >> 2);
                    const int c0 = n * 64 + wn * 16 + ni * 8 + (lane & 3) * 2;
                    float2 g0 = *reinterpret_cast<const float2*>(&gx[(size_t)r0 * NA + c0]);
                    float2 g1 = *reinterpret_cast<const float2*>(&gx[(size_t)(r0 + 8) * NA + c0]);
                    *reinterpret_cast<float2*>(&d_Y1[(size_t)r0 * NA + c0]) =
                        make_float2(acc[mi][ni][0] + g0.x, acc[mi][ni][1] + g0.y);
                    *reinterpret_cast<float2*>(&d_Y1[(size_t)(r0 + 8) * NA + c0]) =
                        make_float2(acc[mi][ni][2] + g1.x, acc[mi][ni][3] + g1.y);
                }
        }
        gbar();

        // -------- P2: boundary gate + LSTM1 (1 CTA per batch row)
        if (cta < B_) {
            const int b = cta;
            const float* Yb = d_Y1 + (size_t)b * NA;
            float p = Yb[G4 + tid] * vs[tid] + Yb[G4 + 256 + tid] * vs[256 + tid];
            red[tid] = p;
            __syncthreads();
            for (int off = 128; off > 0; off >>= 1) {
                if (tid < off) red[tid] += red[tid + off];
                __syncthreads();
            }
            float s = rintf(1.f / (1.f + expf(-red[0])));
            if (tid == 0) d_s[b] = s;
            for (int j = tid; j < H_; j += 256) {
                float gi = Yb[j], gf = Yb[H_ + j], gg = Yb[2 * H_ + j], go = Yb[3 * H_ + j];
                float c = sigm(gf) * d_c1[b * H_ + j] + sigm(gi) * tanhf(gg);
                float h = sigm(go) * tanhf(c);
                d_c1r[b * H_ + j] = c;
                d_h1r[b * H_ + j] = h;
                float v = h * s;
                __half hi = __float2half(v);
                __half lo = __float2half(v - __half2float(hi));
                d_STH[b * K2 + j] = hi;
                d_STL[b * K2 + j] = lo;
            }
        }
        gbar();

        // -------- P3: Y2 = [h1r*s | h2] @ [Wih2|Whh2]^T  (128 tiles of 64x64)
        if (cta < 128) {
            const int m = cta / 64, n = cta % 64;
            float acc[2][2][4];
#pragma unroll
            for (int i = 0; i < 2; i++)
#pragma unroll
                for (int j = 0; j < 2; j++)
#pragma unroll
                    for (int q = 0; q < 4; q++) acc[i][j][q] = 0.f;
            tile_mm(d_STH + (size_t)(m * 64) * K2, d_STL + (size_t)(m * 64) * K2, K2,
                    d_WbH + (size_t)(n * 64) * K2, d_WbL + (size_t)(n * 64) * K2, K2,
                    K2 / 32, sbase, acc, tid, wm, wn, rsel, csel);
#pragma unroll
            for (int mi = 0; mi < 2; mi++)
#pragma unroll
                for (int ni = 0; ni < 2; ni++) {
                    const int r0 = m * 64 + wm * 32 + mi * 16 + (lane >> 2);
                    const int c0 = n * 64 + wn * 16 + ni * 8 + (lane & 3) * 2;
                    *reinterpret_cast<float2*>(&d_Y2[(size_t)r0 * G4 + c0]) =
                        make_float2(acc[mi][ni][0], acc[mi][ni][1]);
                    *reinterpret_cast<float2*>(&d_Y2[(size_t)(r0 + 8) * G4 + c0]) =
                        make_float2(acc[mi][ni][2], acc[mi][ni][3]);
                }
        }
        gbar();

        // -------- P4: LSTM2 + state commit
        if (cta < B_) {
            const int b = cta;
            const float* Yb = d_Y2 + (size_t)b * G4;
            const float s = d_s[b];
            for (int j = tid; j < H_; j += 256) {
                const int idx = b * H_ + j;
                float gi = Yb[j], gf = Yb[H_ + j], gg = Yb[2 * H_ + j], go = Yb[3 * H_ + j];
                float c = sigm(gf) * d_c2[idx] + sigm(gi) * tanhf(gg);
                float h = sigm(go) * tanhf(c);
                d_c2[idx] = c;
                if (t == T_ - 1) out[idx] = h;
                {
                    __half hi = __float2half(h);
                    __half lo = __float2half(h - __half2float(hi));
                    d_STH[b * K2 + H_ + j] = hi;
                    d_STL[b * K2 + H_ + j] = lo;
                }
                float h1 = d_h1r[idx] * (1.f - s);
                d_c1[idx] = d_c1r[idx] * (1.f - s);
                {
                    __half hi = __float2half(h1);
                    __half lo = __float2half(h1 - __half2float(hi));
                    d_AhH[idx] = hi;
                    d_AhL[idx] = lo;
                }
            }
        }
        gbar();
    }
}

// ---------------- split / pack / zero kernels --------------------------------
__global__ void split_w(const float* __restrict__ S1, const float* __restrict__ S2,
                        __half* __restrict__ Hh, __half* __restrict__ Ll,
                        int KSHIFT, int mode, size_t total)
{
    size_t idx = (size_t)blockIdx.x * blockDim.x + threadIdx.x;
    if (idx >= total) return;
    const int K = 1 << KSHIFT;
    const int n = (int)(idx >> KSHIFT);
    const int k = (int)(idx & (K - 1));
    float v;
    if (mode == 0)      v = (n < G4) ? S1[idx] : S2[idx - (size_t)G4 * K];
    else if (mode == 1) v = (k < H_) ? S1[((size_t)n << 10) + k] : S2[((size_t)n << 10) + k - H_];
    else                v = S1[idx];
    __half hi = __float2half(v);
    __half lo = __float2half(v - __half2float(hi));
    Hh[idx] = hi; Ll[idx] = lo;
}

__global__ void pack_bias(const float* __restrict__ b1, const float* __restrict__ bbd)
{
    int i = blockIdx.x * blockDim.x + threadIdx.x;
    if (i < NA) d_bx[i] = (i < G4) ? b1[i] : bbd[i - G4];
}

__global__ void zero_state()
{
    int i = blockIdx.x * blockDim.x + threadIdx.x;
    __half z = __float2half(0.f);
    if (i < B_ * H_) { d_c1[i] = 0.f; d_c2[i] = 0.f; d_AhH[i] = z; d_AhL[i] = z; }
    if (i < B_ * K2) { d_STH[i] = z; d_STL[i] = z; }
    if (i < 260) d_bars[i] = 0u;
}

// ---------------- launch -----------------------------------------------------
extern "C" void kernel_launch(void* const* d_in, const int* in_sizes, int n_in,
                              void* d_out, int out_size)
{
    const float* video = (const float*)d_in[0];
    const float* Wemb  = (const float*)d_in[1];
    const float* bemb  = (const float*)d_in[2];
    const float* Wih1  = (const float*)d_in[3];
    const float* Whh1  = (const float*)d_in[4];
    const float* b1    = (const float*)d_in[5];
    const float* Wsi   = (const float*)d_in[6];
    const float* Wsh   = (const float*)d_in[7];
    const float* bbd   = (const float*)d_in[8];
    const float* vs    = (const float*)d_in[9];
    const float* Wih2  = (const float*)d_in[10];
    const float* Whh2  = (const float*)d_in[11];

    __half *pVidH,*pVidL,*pWembH,*pWembL,*pVH,*pVL,*pWxH,*pWxL,*pWhH,*pWhL,*pWbH,*pWbL;
    float *pbx,*pGXZ;
    cudaGetSymbolAddress((void**)&pVidH, d_VidH);  cudaGetSymbolAddress((void**)&pVidL, d_VidL);
    cudaGetSymbolAddress((void**)&pWembH,d_WembH); cudaGetSymbolAddress((void**)&pWembL,d_WembL);
    cudaGetSymbolAddress((void**)&pVH,   d_VH);    cudaGetSymbolAddress((void**)&pVL,   d_VL);
    cudaGetSymbolAddress((void**)&pWxH,  d_WxH);   cudaGetSymbolAddress((void**)&pWxL,  d_WxL);
    cudaGetSymbolAddress((void**)&pWhH,  d_WhH);   cudaGetSymbolAddress((void**)&pWhL,  d_WhL);
    cudaGetSymbolAddress((void**)&pWbH,  d_WbH);   cudaGetSymbolAddress((void**)&pWbL,  d_WbL);
    cudaGetSymbolAddress((void**)&pbx,   d_bx);
    cudaGetSymbolAddress((void**)&pGXZ,  d_GXZ);

    cudaFuncSetAttribute(gemm_h<1,1,1>, cudaFuncAttributeMaxDynamicSharedMemorySize, SMEM_TOT);
    cudaFuncSetAttribute(gemm_h<1,0,0>, cudaFuncAttributeMaxDynamicSharedMemorySize, SMEM_TOT);

    zero_state<<<(B_*K2 + 255) / 256, 256>>>();
    pack_bias<<<(NA + 255) / 256, 256>>>(b1, bbd);
    {
        size_t n;
        n = (size_t)H_ * F_;   split_w<<<(int)((n + 255) / 256), 256>>>(Wemb,  nullptr, pWembH, pWembL, 11, 2, n);
        n = (size_t)NA * H_;   split_w<<<(int)((n + 255) / 256), 256>>>(Wih1,  Wsi,     pWxH,   pWxL,   10, 0, n);
        n = (size_t)NA * H_;   split_w<<<(int)((n + 255) / 256), 256>>>(Whh1,  Wsh,     pWhH,   pWhL,   10, 0, n);
        n = (size_t)G4 * K2;   split_w<<<(int)((n + 255) / 256), 256>>>(Wih2,  Whh2,    pWbH,   pWbL,   11, 1, n);
        n = (size_t)B_*T_*F_;  split_w<<<(int)((n + 255) / 256), 256>>>(video, nullptr, pVidH,  pVidL,  11, 2, n);
    }

    // V = relu(video @ Wemb^T + bemb) -> fp16 split (rows b*T+t)
    gemm_h<1,1,1><<<dim3(H_/128, (B_*T_)/64), 256, SMEM_TOT>>>(
        pVidH, pVidL, (size_t)64 * F_, (size_t)128 * F_, F_,
        pWembH, pWembL, nullptr, bemb, pVH, pVL, F_, H_);
    // GXZ[t*B+b] = V[b*T+t] @ [Wih1;Wsi]^T + [b1;b_bd]
    gemm_h<1,0,0><<<dim3(NA/128, (B_*T_)/64), 256, SMEM_TOT>>>(
        pVH, pVL, (size_t)64 * T_ * H_, (size_t)H_, T_ * H_,
        pWxH, pWxL, pGXZ, pbx, nullptr, nullptr, H_, NA);

    // persistent fused scan over T
    scan_persist<<<NCTA, 256>>>(vs, (float*)d_out);
}

// round 8
// speedup vs baseline: 2.4864x; 1.5460x over previous
#include <cuda_runtime.h>
#include <cuda_fp16.h>
#include <math.h>
#include <stdint.h>

#define B_  128
#define T_  64
#define F_  2048
#define H_  1024
#define M_  512
#define G4  4096   // 4*H
#define NA  4608   // 4H + M
#define K2  2048   // 2H

// ---------------- device scratch (no allocations allowed) -------------------
__device__ __align__(128) __half d_VidH[(size_t)B_*T_*F_];
__device__ __align__(128) __half d_VidL[(size_t)B_*T_*F_];
__device__ __align__(128) __half d_WembH[(size_t)H_*F_];
__device__ __align__(128) __half d_WembL[(size_t)H_*F_];
__device__ __align__(128) __half d_VH[(size_t)B_*T_*H_];     // relu(embed) split, rows b*T+t
__device__ __align__(128) __half d_VL[(size_t)B_*T_*H_];
__device__ __align__(128) __half d_WxH[(size_t)NA*H_];       // [W_ih1; Wsi]
__device__ __align__(128) __half d_WxL[(size_t)NA*H_];
__device__ __align__(128) __half d_WhH[(size_t)NA*H_];       // [W_hh1; Wsh]
__device__ __align__(128) __half d_WhL[(size_t)NA*H_];
__device__ __align__(128) __half d_WbH[(size_t)G4*K2];       // [W_ih2 | W_hh2]
__device__ __align__(128) __half d_WbL[(size_t)G4*K2];
__device__ __align__(128) __half d_AhH[B_*H_];               // h1 split (Y1 A)
__device__ __align__(128) __half d_AhL[B_*H_];
__device__ __align__(128) __half d_STH[B_*K2];               // [h1r*s | h2] (Y2 A)
__device__ __align__(128) __half d_STL[B_*K2];

__device__ float d_bx [NA];
__device__ float d_GXZ[(size_t)B_*T_*NA];    // rows t*B+b
__device__ float d_Y1 [B_*NA];
__device__ float d_Y2 [B_*G4];
__device__ float d_c1 [B_*H_];
__device__ float d_c2 [B_*H_];
__device__ float d_h1r[B_*H_];
__device__ float d_c1r[B_*H_];
__device__ float d_s  [B_];
__device__ unsigned int d_bars[260];

// ---------------- asm helpers ------------------------------------------------
__device__ __forceinline__ uint32_t s2u_(const void* p) {
    uint32_t a;
    asm("{ .reg .u64 t; cvta.to.shared.u64 t, %1; cvt.u32.u64 %0, t; }" : "=r"(a) : "l"(p));
    return a;
}
__device__ __forceinline__ void cp16_(uint32_t d, const void* s) {
    asm volatile("cp.async.cg.shared.global [%0], [%1], 16;" :: "r"(d), "l"(s));
}
__device__ __forceinline__ void ldsm4_(uint32_t a, uint32_t& r0, uint32_t& r1, uint32_t& r2, uint32_t& r3) {
    asm volatile("ldmatrix.sync.aligned.m8n8.x4.shared.b16 {%0,%1,%2,%3}, [%4];"
                 : "=r"(r0), "=r"(r1), "=r"(r2), "=r"(r3) : "r"(a));
}
__device__ __forceinline__ void hmma_(float* c, const uint32_t* a, const uint32_t* b) {
    asm volatile("mma.sync.aligned.m16n8k16.row.col.f32.f16.f16.f32 "
                 "{%0,%1,%2,%3}, {%4,%5,%6,%7}, {%8,%9}, {%0,%1,%2,%3};"
                 : "+f"(c[0]), "+f"(c[1]), "+f"(c[2]), "+f"(c[3])
                 : "r"(a[0]), "r"(a[1]), "r"(a[2]), "r"(a[3]), "r"(b[0]), "r"(b[1]));
}
__device__ __forceinline__ float sigm(float x) { return 1.f / (1.f + expf(-x)); }

// ---------------- precompute HMMA GEMM (64x128 tiles, proven in R6) ----------
constexpr int STAGE_B = 30720;
constexpr int SMEM_TOT = 2 * STAGE_B;
constexpr int OB_B = 10240;

template<int HAS_BIAS, int RELU, int SPLIT_OUT>
__global__ __launch_bounds__(256)
void gemm_h(const __half* __restrict__ AH, const __half* __restrict__ AL,
            size_t aS1, size_t aS2, int lda,
            const __half* __restrict__ BH, const __half* __restrict__ BL,
            float* __restrict__ C,
            const float* __restrict__ bias,
            __half* __restrict__ OH, __half* __restrict__ OL,
            int K, int N)
{
    extern __shared__ __align__(128) char sm[];
    const uint32_t sb = s2u_(sm);
    const int tid  = threadIdx.x;
    const int lane = tid & 31;
    const int wid  = tid >> 5;
    const int wm   = wid & 1;
    const int wn   = wid >> 1;
    const int bx   = blockIdx.x, by = blockIdx.y;

    const size_t aOff = (size_t)(by & 1) * aS1 + (size_t)(by >> 1) * aS2;
    const __half* gAH = AH + aOff;
    const __half* gAL = AL + aOff;
    const __half* gBH = BH + (size_t)bx * 128 * K;
    const __half* gBL = BL + (size_t)bx * 128 * K;

    float acc[2][4][4];
#pragma unroll
    for (int i = 0; i < 2; i++)
#pragma unroll
        for (int j = 0; j < 4; j++)
#pragma unroll
            for (int q = 0; q < 4; q++) acc[i][j][q] = 0.f;

    auto load_stage = [&](int p, int kt) {
        const uint32_t dst = sb + p * STAGE_B;
        const int k0 = kt * 32;
#pragma unroll
        for (int i = 0; i < 2; i++) {
            int c = tid * 2 + i;
            int row = c >> 2, col = c & 3;
            const __half* src = (row < 64) ? (gAH + (size_t)row * lda)
                                           : (gAL + (size_t)(row - 64) * lda);
            cp16_(dst + row * 80 + col * 16, src + k0 + col * 8);
        }
#pragma unroll
        for (int i = 0; i < 4; i++) {
            int c = tid * 4 + i;
            int row = c >> 2, col = c & 3;
            const __half* src = (row < 128) ? (gBH + (size_t)row * K)
                                            : (gBL + (size_t)(row - 128) * K);
            cp16_(dst + OB_B + row * 80 + col * 16, src + k0 + col * 8);
        }
        asm volatile("cp.async.commit_group;" ::: "memory");
    };

    const int KT = K / 32;
    load_stage(0, 0);
    const int rsel = lane & 15, csel = lane >> 4;

    for (int kt = 0; kt < KT; kt++) {
        const int p = kt & 1;
        if (kt + 1 < KT) {
            load_stage(p ^ 1, kt + 1);
            asm volatile("cp.async.wait_group 1;" ::: "memory");
        } else {
            asm volatile("cp.async.wait_group 0;" ::: "memory");
        }
        __syncthreads();
        const uint32_t stg = sb + p * STAGE_B;
#pragma unroll
        for (int h = 0; h < 2; h++) {
            uint32_t aH[2][4], aL[2][4], bHf[4][2], bLf[4][2];
#pragma unroll
            for (int mi = 0; mi < 2; mi++) {
                int row = wm * 32 + mi * 16 + rsel;
                uint32_t ad = stg + row * 80 + h * 32 + csel * 16;
                ldsm4_(ad,        aH[mi][0], aH[mi][1], aH[mi][2], aH[mi][3]);
                ldsm4_(ad + 5120, aL[mi][0], aL[mi][1], aL[mi][2], aL[mi][3]);
            }
#pragma unroll
            for (int g = 0; g < 2; g++) {
                int row = wn * 32 + g * 16 + rsel;
                uint32_t bd = stg + OB_B + row * 80 + h * 32 + csel * 16;
                uint32_t t0, t1, t2, t3;
                ldsm4_(bd, t0, t1, t2, t3);
                bHf[g*2][0] = t0; bHf[g*2][1] = t2; bHf[g*2+1][0] = t1; bHf[g*2+1][1] = t3;
                ldsm4_(bd + 10240, t0, t1, t2, t3);
                bLf[g*2][0] = t0; bLf[g*2][1] = t2; bLf[g*2+1][0] = t1; bLf[g*2+1][1] = t3;
            }
#pragma unroll
            for (int mi = 0; mi < 2; mi++)
#pragma unroll
                for (int ni = 0; ni < 4; ni++) {
                    hmma_(acc[mi][ni], aH[mi], bHf[ni]);
                    hmma_(acc[mi][ni], aH[mi], bLf[ni]);
                    hmma_(acc[mi][ni], aL[mi], bHf[ni]);
                }
        }
        __syncthreads();
    }

#pragma unroll
    for (int mi = 0; mi < 2; mi++)
#pragma unroll
        for (int ni = 0; ni < 4; ni++) {
            const int row0 = by * 64 + wm * 32 + mi * 16 + (lane >> 2);
            const int col  = bx * 128 + wn * 32 + ni * 8 + (lane & 3) * 2;
            float v[4];
#pragma unroll
            for (int q = 0; q < 4; q++) v[q] = acc[mi][ni][q];
            if (HAS_BIAS) {
                float b0 = bias[col], b1 = bias[col + 1];
                v[0] += b0; v[1] += b1; v[2] += b0; v[3] += b1;
            }
            if (RELU) {
#pragma unroll
                for (int q = 0; q < 4; q++) v[q] = fmaxf(v[q], 0.f);
            }
            if (SPLIT_OUT) {
#pragma unroll
                for (int q = 0; q < 4; q++) {
                    int r = row0 + (q >> 1) * 8, c = col + (q & 1);
                    __half hi = __float2half(v[q]);
                    __half lo = __float2half(v[q] - __half2float(hi));
                    OH[(size_t)r * N + c] = hi;
                    OL[(size_t)r * N + c] = lo;
                }
            } else {
                *reinterpret_cast<float2*>(&C[(size_t)row0 * N + col])       = make_float2(v[0], v[1]);
                *reinterpret_cast<float2*>(&C[(size_t)(row0 + 8) * N + col]) = make_float2(v[2], v[3]);
            }
        }
}

// ---------------- persistent scan -------------------------------------------
// 32x64 tile, 8 warps (2 along M x 4 along N, warp 16x16), 3-stage pipeline.
// stage layout: A 64 rows(32 hi + 32 lo) x 80B = 5120; B 128 rows(64 hi+64 lo) x 80B = 10240
constexpr int SSTG = 15360;

struct ScanSmem {
    __align__(128) char stg[3][SSTG];
    float red[256];
};

__device__ __forceinline__ void tile_mm32(
    const __half* __restrict__ AH, const __half* __restrict__ AL, int lda,
    const __half* __restrict__ BH, const __half* __restrict__ BL, int ldb,
    int KT, uint32_t sbase, float acc[2][4],
    int tid, int wm, int wn, int rsel, int csel)
{
    auto load_stage = [&](int p, int kt) {
        const uint32_t dst = sbase + p * SSTG;
        const int k0 = kt * 32;
        {   // A: 256 chunks of 16B, 1 per thread
            int row = tid >> 2, col = tid & 3;
            const __half* src = (row < 32) ? AH + (size_t)row * lda
                                           : AL + (size_t)(row - 32) * lda;
            cp16_(dst + row * 80 + col * 16, src + k0 + col * 8);
        }
#pragma unroll
        for (int i = 0; i < 2; i++) {   // B: 512 chunks
            int c = tid * 2 + i;
            int row = c >> 2, col = c & 3;
            const __half* src = (row < 64) ? BH + (size_t)row * ldb
                                           : BL + (size_t)(row - 64) * ldb;
            cp16_(dst + 5120 + row * 80 + col * 16, src + k0 + col * 8);
        }
        asm volatile("cp.async.commit_group;" ::: "memory");
    };

    load_stage(0, 0);
    if (KT > 1) load_stage(1, 1);

    for (int kt = 0; kt < KT; kt++) {
        if (kt + 2 < KT) {
            load_stage((kt + 2) % 3, kt + 2);
            asm volatile("cp.async.wait_group 2;" ::: "memory");
        } else if (kt + 1 < KT) {
            asm volatile("cp.async.wait_group 1;" ::: "memory");
        } else {
            asm volatile("cp.async.wait_group 0;" ::: "memory");
        }
        __syncthreads();

        const uint32_t stg = sbase + (kt % 3) * SSTG;
#pragma unroll
        for (int h = 0; h < 2; h++) {
            uint32_t aH[4], aL[4], bH[2][2], bL[2][2];
            {
                uint32_t ad = stg + (wm * 16 + rsel) * 80 + h * 32 + csel * 16;
                ldsm4_(ad,        aH[0], aH[1], aH[2], aH[3]);
                ldsm4_(ad + 2560, aL[0], aL[1], aL[2], aL[3]);
            }
            {
                uint32_t bd = stg + 5120 + (wn * 16 + rsel) * 80 + h * 32 + csel * 16;
                uint32_t t0, t1, t2, t3;
                ldsm4_(bd, t0, t1, t2, t3);
                bH[0][0] = t0; bH[0][1] = t2; bH[1][0] = t1; bH[1][1] = t3;
                ldsm4_(bd + 5120, t0, t1, t2, t3);
                bL[0][0] = t0; bL[0][1] = t2; bL[1][0] = t1; bL[1][1] = t3;
            }
#pragma unroll
            for (int ni = 0; ni < 2; ni++) {
                hmma_(acc[ni], aH, bH[ni]);
                hmma_(acc[ni], aH, bL[ni]);
                hmma_(acc[ni], aL, bH[ni]);
            }
        }
        __syncthreads();
    }
}

__global__ __launch_bounds__(256, 2)
void scan_persist(const float* __restrict__ vs, float* __restrict__ out)
{
    __shared__ ScanSmem sm;
    const uint32_t sbase = s2u_(&sm.stg[0][0]);
    const int tid  = threadIdx.x;
    const int lane = tid & 31;
    const int wid  = tid >> 5;
    const int wm   = wid & 1, wn = wid >> 1;
    const int rsel = lane & 15, csel = lane >> 4;
    const int cta  = blockIdx.x;
    const int G    = gridDim.x;
    int bar = 0;

    auto gbar = [&]() {
        __threadfence();
        __syncthreads();
        if (tid == 0) {
            atomicAdd(&d_bars[bar], 1u);
            while (*((volatile unsigned int*)&d_bars[bar]) < (unsigned)G) { }
        }
        bar++;
        __syncthreads();
        __threadfence();
    };

    for (int t = 0; t < T_; t++) {
        // ---- P1: Y1 = h1 @ [Whh1;Wsh]^T + GXZ[t]   (288 tiles of 32x64)
        for (int tile = cta; tile < 288; tile += G) {
            const int m = tile & 3, n = tile >> 2;
            float acc[2][4];
#pragma unroll
            for (int j = 0; j < 2; j++)
#pragma unroll
                for (int q = 0; q < 4; q++) acc[j][q] = 0.f;
            tile_mm32(d_AhH + (size_t)(m * 32) * H_, d_AhL + (size_t)(m * 32) * H_, H_,
                      d_WhH + (size_t)(n * 64) * H_, d_WhL + (size_t)(n * 64) * H_, H_,
                      H_ / 32, sbase, acc, tid, wm, wn, rsel, csel);
            const float* gx = d_GXZ + (size_t)t * B_ * NA;
#pragma unroll
            for (int ni = 0; ni < 2; ni++) {
                const int r0 = m * 32 + wm * 16 + (lane >> 2);
                const int c0 = n * 64 + wn * 16 + ni * 8 + (lane & 3) * 2;
                float2 g0 = *reinterpret_cast<const float2*>(&gx[(size_t)r0 * NA + c0]);
                float2 g1 = *reinterpret_cast<const float2*>(&gx[(size_t)(r0 + 8) * NA + c0]);
                *reinterpret_cast<float2*>(&d_Y1[(size_t)r0 * NA + c0]) =
                    make_float2(acc[ni][0] + g0.x, acc[ni][1] + g0.y);
                *reinterpret_cast<float2*>(&d_Y1[(size_t)(r0 + 8) * NA + c0]) =
                    make_float2(acc[ni][2] + g1.x, acc[ni][3] + g1.y);
            }
        }
        gbar();

        // ---- P2: boundary gate + LSTM1
        for (int b = cta; b < B_; b += G) {
            const float* Yb = d_Y1 + (size_t)b * NA;
            float p = Yb[G4 + tid] * vs[tid] + Yb[G4 + 256 + tid] * vs[256 + tid];
            sm.red[tid] = p;
            __syncthreads();
            for (int off = 128; off > 0; off >>= 1) {
                if (tid < off) sm.red[tid] += sm.red[tid + off];
                __syncthreads();
            }
            float s = rintf(1.f / (1.f + expf(-sm.red[0])));
            if (tid == 0) d_s[b] = s;
            __syncthreads();
            for (int j = tid; j < H_; j += 256) {
                float gi = Yb[j], gf = Yb[H_ + j], gg = Yb[2 * H_ + j], go = Yb[3 * H_ + j];
                float c = sigm(gf) * d_c1[b * H_ + j] + sigm(gi) * tanhf(gg);
                float h = sigm(go) * tanhf(c);
                d_c1r[b * H_ + j] = c;
                d_h1r[b * H_ + j] = h;
                float v = h * s;
                __half hi = __float2half(v);
                __half lo = __float2half(v - __half2float(hi));
                d_STH[b * K2 + j] = hi;
                d_STL[b * K2 + j] = lo;
            }
        }
        gbar();

        // ---- P3: Y2 = [h1r*s | h2] @ [Wih2|Whh2]^T   (256 tiles of 32x64)
        for (int tile = cta; tile < 256; tile += G) {
            const int m = tile & 3, n = tile >> 2;
            float acc[2][4];
#pragma unroll
            for (int j = 0; j < 2; j++)
#pragma unroll
                for (int q = 0; q < 4; q++) acc[j][q] = 0.f;
            tile_mm32(d_STH + (size_t)(m * 32) * K2, d_STL + (size_t)(m * 32) * K2, K2,
                      d_WbH + (size_t)(n * 64) * K2, d_WbL + (size_t)(n * 64) * K2, K2,
                      K2 / 32, sbase, acc, tid, wm, wn, rsel, csel);
#pragma unroll
            for (int ni = 0; ni < 2; ni++) {
                const int r0 = m * 32 + wm * 16 + (lane >> 2);
                const int c0 = n * 64 + wn * 16 + ni * 8 + (lane & 3) * 2;
                *reinterpret_cast<float2*>(&d_Y2[(size_t)r0 * G4 + c0]) =
                    make_float2(acc[ni][0], acc[ni][1]);
                *reinterpret_cast<float2*>(&d_Y2[(size_t)(r0 + 8) * G4 + c0]) =
                    make_float2(acc[ni][2], acc[ni][3]);
            }
        }
        gbar();

        // ---- P4: LSTM2 + state commit
        for (int b = cta; b < B_; b += G) {
            const float* Yb = d_Y2 + (size_t)b * G4;
            const float s = d_s[b];
            for (int j = tid; j < H_; j += 256) {
                const int idx = b * H_ + j;
                float gi = Yb[j], gf = Yb[H_ + j], gg = Yb[2 * H_ + j], go = Yb[3 * H_ + j];
                float c = sigm(gf) * d_c2[idx] + sigm(gi) * tanhf(gg);
                float h = sigm(go) * tanhf(c);
                d_c2[idx] = c;
                if (t == T_ - 1) out[idx] = h;
                {
                    __half hi = __float2half(h);
                    __half lo = __float2half(h - __half2float(hi));
                    d_STH[b * K2 + H_ + j] = hi;
                    d_STL[b * K2 + H_ + j] = lo;
                }
                float h1 = d_h1r[idx] * (1.f - s);
                d_c1[idx] = d_c1r[idx] * (1.f - s);
                {
                    __half hi = __float2half(h1);
                    __half lo = __float2half(h1 - __half2float(hi));
                    d_AhH[idx] = hi;
                    d_AhL[idx] = lo;
                }
            }
        }
        gbar();
    }
}

// ---------------- split / pack / zero kernels --------------------------------
__global__ void split_w(const float* __restrict__ S1, const float* __restrict__ S2,
                        __half* __restrict__ Hh, __half* __restrict__ Ll,
                        int KSHIFT, int mode, size_t total)
{
    size_t idx = (size_t)blockIdx.x * blockDim.x + threadIdx.x;
    if (idx >= total) return;
    const int K = 1 << KSHIFT;
    const int n = (int)(idx >> KSHIFT);
    const int k = (int)(idx & (K - 1));
    float v;
    if (mode == 0)      v = (n < G4) ? S1[idx] : S2[idx - (size_t)G4 * K];
    else if (mode == 1) v = (k < H_) ? S1[((size_t)n << 10) + k] : S2[((size_t)n << 10) + k - H_];
    else                v = S1[idx];
    __half hi = __float2half(v);
    __half lo = __float2half(v - __half2float(hi));
    Hh[idx] = hi; Ll[idx] = lo;
}

__global__ void pack_bias(const float* __restrict__ b1, const float* __restrict__ bbd)
{
    int i = blockIdx.x * blockDim.x + threadIdx.x;
    if (i < NA) d_bx[i] = (i < G4) ? b1[i] : bbd[i - G4];
}

__global__ void zero_state()
{
    int i = blockIdx.x * blockDim.x + threadIdx.x;
    __half z = __float2half(0.f);
    if (i < B_ * H_) { d_c1[i] = 0.f; d_c2[i] = 0.f; d_AhH[i] = z; d_AhL[i] = z; }
    if (i < B_ * K2) { d_STH[i] = z; d_STL[i] = z; }
    if (i < 260) d_bars[i] = 0u;
}

// ---------------- launch -----------------------------------------------------
extern "C" void kernel_launch(void* const* d_in, const int* in_sizes, int n_in,
                              void* d_out, int out_size)
{
    const float* video = (const float*)d_in[0];
    const float* Wemb  = (const float*)d_in[1];
    const float* bemb  = (const float*)d_in[2];
    const float* Wih1  = (const float*)d_in[3];
    const float* Whh1  = (const float*)d_in[4];
    const float* b1    = (const float*)d_in[5];
    const float* Wsi   = (const float*)d_in[6];
    const float* Wsh   = (const float*)d_in[7];
    const float* bbd   = (const float*)d_in[8];
    const float* vs    = (const float*)d_in[9];
    const float* Wih2  = (const float*)d_in[10];
    const float* Whh2  = (const float*)d_in[11];

    __half *pVidH,*pVidL,*pWembH,*pWembL,*pVH,*pVL,*pWxH,*pWxL,*pWhH,*pWhL,*pWbH,*pWbL;
    float *pbx,*pGXZ;
    cudaGetSymbolAddress((void**)&pVidH, d_VidH);  cudaGetSymbolAddress((void**)&pVidL, d_VidL);
    cudaGetSymbolAddress((void**)&pWembH,d_WembH); cudaGetSymbolAddress((void**)&pWembL,d_WembL);
    cudaGetSymbolAddress((void**)&pVH,   d_VH);    cudaGetSymbolAddress((void**)&pVL,   d_VL);
    cudaGetSymbolAddress((void**)&pWxH,  d_WxH);   cudaGetSymbolAddress((void**)&pWxL,  d_WxL);
    cudaGetSymbolAddress((void**)&pWhH,  d_WhH);   cudaGetSymbolAddress((void**)&pWhL,  d_WhL);
    cudaGetSymbolAddress((void**)&pWbH,  d_WbH);   cudaGetSymbolAddress((void**)&pWbL,  d_WbL);
    cudaGetSymbolAddress((void**)&pbx,   d_bx);
    cudaGetSymbolAddress((void**)&pGXZ,  d_GXZ);

    cudaFuncSetAttribute(gemm_h<1,1,1>, cudaFuncAttributeMaxDynamicSharedMemorySize, SMEM_TOT);
    cudaFuncSetAttribute(gemm_h<1,0,0>, cudaFuncAttributeMaxDynamicSharedMemorySize, SMEM_TOT);
    cudaFuncSetAttribute(scan_persist, cudaFuncAttributePreferredSharedMemoryCarveout,
                         cudaSharedmemCarveoutMaxShared);

    // deterministic grid size: all CTAs resident (required by the spin barrier)
    int nsm = 148, occ = 2;
    cudaDeviceGetAttribute(&nsm, cudaDevAttrMultiProcessorCount, 0);
    cudaOccupancyMaxActiveBlocksPerMultiprocessor(&occ, scan_persist, 256, 0);
    if (occ < 1) occ = 1;
    if (occ > 2) occ = 2;
    const int G = nsm * occ;

    zero_state<<<(B_*K2 + 255) / 256, 256>>>();
    pack_bias<<<(NA + 255) / 256, 256>>>(b1, bbd);
    {
        size_t n;
        n = (size_t)H_ * F_;   split_w<<<(int)((n + 255) / 256), 256>>>(Wemb,  nullptr, pWembH, pWembL, 11, 2, n);
        n = (size_t)NA * H_;   split_w<<<(int)((n + 255) / 256), 256>>>(Wih1,  Wsi,     pWxH,   pWxL,   10, 0, n);
        n = (size_t)NA * H_;   split_w<<<(int)((n + 255) / 256), 256>>>(Whh1,  Wsh,     pWhH,   pWhL,   10, 0, n);
        n = (size_t)G4 * K2;   split_w<<<(int)((n + 255) / 256), 256>>>(Wih2,  Whh2,    pWbH,   pWbL,   11, 1, n);
        n = (size_t)B_*T_*F_;  split_w<<<(int)((n + 255) / 256), 256>>>(video, nullptr, pVidH,  pVidL,  11, 2, n);
    }

    // V = relu(video @ Wemb^T + bemb) -> fp16 split (rows b*T+t)
    gemm_h<1,1,1><<<dim3(H_/128, (B_*T_)/64), 256, SMEM_TOT>>>(
        pVidH, pVidL, (size_t)64 * F_, (size_t)128 * F_, F_,
        pWembH, pWembL, nullptr, bemb, pVH, pVL, F_, H_);
    // GXZ[t*B+b] = V[b*T+t] @ [Wih1;Wsi]^T + [b1;b_bd]
    gemm_h<1,0,0><<<dim3(NA/128, (B_*T_)/64), 256, SMEM_TOT>>>(
        pVH, pVL, (size_t)64 * T_ * H_, (size_t)H_, T_ * H_,
        pWxH, pWxL, pGXZ, pbx, nullptr, nullptr, H_, NA);

    // persistent fused scan over T
    scan_persist<<<G, 256>>>(vs, (float*)d_out);
}